// round 12
// baseline (speedup 1.0000x reference)
#include <cuda_runtime.h>
#include <cuda_fp16.h>
#include <cstdint>
#include <cstddef>

#define N_NODES   100000
#define N_EDGES   1600000
#define DIM       128
#define N_CLASSES 10

#define SCAN_BS   1024
#define SCAN_NB   ((N_NODES + SCAN_BS - 1) / SCAN_BS)   // 98 (<=128)

// ---------------- scratch (static __device__, no allocation) ----------------
__device__ __half g_bufH[(size_t)N_NODES * DIM];   // GEMM out h (gather target)
__device__ __half g_bufP[(size_t)N_NODES * DIM];   // aggregate out (GEMM A input)
__device__ __half g_Wt[4][DIM * DIM];              // transposed fp16 weights [n][k]
__device__ float  g_dinv[N_NODES];
__device__ int    g_cnt[N_NODES];                  // real-edge in-degree
__device__ int    g_off[N_NODES + 1];
__device__ int    g_cur[N_NODES];
__device__ int2   g_edge[N_EDGES];                 // (src, norm bits)
__device__ int    g_bsum[SCAN_NB];
__device__ int    g_bpref[SCAN_NB];

// ---------------- prep kernels ----------------
__global__ void k_count_deg(const int* __restrict__ dst, int e) {
    int i = blockIdx.x * blockDim.x + threadIdx.x;
    if (i < e) atomicAdd(&g_cnt[dst[i]], 1);
}
// scan1 + dinv fused: per-block inclusive scan of cnt, dinv = rsqrt(cnt+1)
__global__ void k_scan1(int n) {
    __shared__ int sh[SCAN_BS];
    int i = blockIdx.x * SCAN_BS + threadIdx.x;
    int c = (i < n) ? g_cnt[i] : 0;
    if (i < n) g_dinv[i] = rsqrtf((float)(c + 1));
    sh[threadIdx.x] = c;
    __syncthreads();
    for (int ofs = 1; ofs < SCAN_BS; ofs <<= 1) {
        int t = (threadIdx.x >= ofs) ? sh[threadIdx.x - ofs] : 0;
        __syncthreads();
        sh[threadIdx.x] += t;
        __syncthreads();
    }
    if (i < n) g_cur[i] = sh[threadIdx.x];
    if (threadIdx.x == SCAN_BS - 1) g_bsum[blockIdx.x] = sh[SCAN_BS - 1];
}
// parallel exclusive scan of block sums (nb <= 128), one block of 128 threads
__global__ void k_scan2(int nb) {
    __shared__ int wsum[4];
    int t = threadIdx.x;
    int lane = t & 31, w = t >> 5;
    int v = (t < nb) ? g_bsum[t] : 0;
    int inc = v;
#pragma unroll
    for (int ofs = 1; ofs < 32; ofs <<= 1) {
        int u = __shfl_up_sync(0xFFFFFFFF, inc, ofs);
        if (lane >= ofs) inc += u;
    }
    if (lane == 31) wsum[w] = inc;
    __syncthreads();
    int woff = 0;
#pragma unroll
    for (int j = 0; j < 4; ++j) woff += (j < w) ? wsum[j] : 0;
    if (t < nb) g_bpref[t] = woff + inc - v;   // exclusive
}
__global__ void k_scan3(int n) {
    int i = blockIdx.x * SCAN_BS + threadIdx.x;
    if (i >= n) return;
    int inc = g_cur[i] + g_bpref[blockIdx.x];
    int ex = inc - g_cnt[i];
    g_off[i] = ex;
    g_cur[i] = ex;
    if (i == n - 1) g_off[n] = inc;
}
__global__ void k_scatter(const int* __restrict__ src, const int* __restrict__ dst, int e) {
    int i = blockIdx.x * blockDim.x + threadIdx.x;
    if (i >= e) return;
    int s = src[i], d = dst[i];
    int p = atomicAdd(&g_cur[d], 1);
    float nm = g_dinv[s] * g_dinv[d];
    g_edge[p] = make_int2(s, __float_as_int(nm));
}

// one launch transposes all 4 weights: Wt[z][n][k] = fp16(W_z[k][n])
__global__ void k_transW(const float* __restrict__ Wa, const float* __restrict__ Wb,
                         const float* __restrict__ Wc, const float* __restrict__ Wd) {
    __shared__ float tile[32][33];
    const float* W = (blockIdx.z == 0) ? Wa : (blockIdx.z == 1) ? Wb
                   : (blockIdx.z == 2) ? Wc : Wd;
    __half* Wt = g_Wt[blockIdx.z];
    int bn = blockIdx.x * 32, bk = blockIdx.y * 32;
    int tx = threadIdx.x, ty = threadIdx.y;          // 32 x 8
#pragma unroll
    for (int r = 0; r < 32; r += 8)
        tile[ty + r][tx] = W[(size_t)(bk + ty + r) * 128 + bn + tx];
    __syncthreads();
#pragma unroll
    for (int r = 0; r < 32; r += 8)
        Wt[(size_t)(bn + ty + r) * 128 + bk + tx] = __float2half_rn(tile[tx][ty + r]);
}

// ---------------- fp16 mma.sync GEMM: 64x128 tile, 8 warps (2M x 4N), warp tile 32x32 ----------------
#define PADH 136
#define HPAD 129
#define GEMM_SMEM_BYTES ((64 + 128) * PADH * sizeof(__half))                 // 52224
#define HEAD_SMEM_BYTES ((64 * HPAD + 128 * N_CLASSES + N_CLASSES) * 4)      // 38184
#define SMEM_BYTES (HEAD_SMEM_BYTES > GEMM_SMEM_BYTES ? HEAD_SMEM_BYTES : GEMM_SMEM_BYTES)

__device__ __forceinline__ void mma_f16(float c[4], const uint32_t a[4],
                                        uint32_t b0, uint32_t b1) {
    asm volatile(
        "mma.sync.aligned.m16n8k16.row.col.f32.f16.f16.f32 "
        "{%0,%1,%2,%3}, {%4,%5,%6,%7}, {%8,%9}, {%0,%1,%2,%3};"
        : "+f"(c[0]), "+f"(c[1]), "+f"(c[2]), "+f"(c[3])
        : "r"(a[0]), "r"(a[1]), "r"(a[2]), "r"(a[3]), "r"(b0), "r"(b1));
}

__global__ __launch_bounds__(256) void k_gemm_mma(
    const __half* __restrict__ A16, const float* __restrict__ A32,
    const __half* __restrict__ Wt, const float* __restrict__ bias,
    __half* __restrict__ C16,
    const float* __restrict__ W2, const float* __restrict__ b2,
    float* __restrict__ OutF,
    int M, int has_bias, int do_relu, int do_head)
{
    extern __shared__ __half smh[];
    __half* sA = smh;                 // [64][PADH]
    __half* sW = smh + 64 * PADH;     // [128][PADH]  (Wt: [n][k])

    int tid = threadIdx.x;
    int wid = tid >> 5, lane = tid & 31;
    int gID = lane >> 2, tig = lane & 3;
    int row0 = blockIdx.x * 64;

    if (A32) {
        // 64 rows x 32 float4 chunks = 2048
#pragma unroll
        for (int i = 0; i < 8; ++i) {
            int fid = i * 256 + tid;
            int r = fid >> 5, c4 = (fid & 31) << 2;
            float4 v = make_float4(0.f, 0.f, 0.f, 0.f);
            int gr = row0 + r;
            if (gr < M) v = __ldg((const float4*)(A32 + (size_t)gr * 128 + c4));
            __half2 lo = __float22half2_rn(make_float2(v.x, v.y));
            __half2 hi = __float22half2_rn(make_float2(v.z, v.w));
            *(uint2*)(sA + r * PADH + c4) = make_uint2(*(uint32_t*)&lo, *(uint32_t*)&hi);
        }
    } else {
        // 64 rows x 16 uint4 chunks = 1024
#pragma unroll
        for (int i = 0; i < 4; ++i) {
            int fid = i * 256 + tid;
            int r = fid >> 4, c8 = (fid & 15) << 3;
            uint4 v = make_uint4(0, 0, 0, 0);
            int gr = row0 + r;
            if (gr < M) v = __ldg((const uint4*)(A16 + (size_t)gr * 128 + c8));
            *(uint4*)(sA + r * PADH + c8) = v;
        }
    }
    // stage Wt: 128 rows x 16 uint4 chunks = 2048
#pragma unroll
    for (int i = 0; i < 8; ++i) {
        int fid = i * 256 + tid;
        int n = fid >> 4, k8 = (fid & 15) << 3;
        uint4 v = __ldg((const uint4*)(Wt + (size_t)n * 128 + k8));
        *(uint4*)(sW + n * PADH + k8) = v;
    }
    __syncthreads();

    int wm = (wid & 1) * 32;     // warp M origin (0 or 32)
    int wn = (wid >> 1) * 32;    // warp N origin (0,32,64,96)

    float acc[2][4][4];
#pragma unroll
    for (int mf = 0; mf < 2; ++mf)
#pragma unroll
        for (int nf = 0; nf < 4; ++nf)
#pragma unroll
            for (int j = 0; j < 4; ++j) acc[mf][nf][j] = 0.f;

#pragma unroll
    for (int k0 = 0; k0 < 128; k0 += 16) {
        uint32_t a[2][4];
#pragma unroll
        for (int mf = 0; mf < 2; ++mf) {
            int mr = wm + mf * 16;
            a[mf][0] = *(const uint32_t*)(sA + (mr + gID)     * PADH + k0 + 2 * tig);
            a[mf][1] = *(const uint32_t*)(sA + (mr + gID + 8) * PADH + k0 + 2 * tig);
            a[mf][2] = *(const uint32_t*)(sA + (mr + gID)     * PADH + k0 + 2 * tig + 8);
            a[mf][3] = *(const uint32_t*)(sA + (mr + gID + 8) * PADH + k0 + 2 * tig + 8);
        }
#pragma unroll
        for (int nf = 0; nf < 4; ++nf) {
            int nc = wn + nf * 8;
            uint32_t b0 = *(const uint32_t*)(sW + (nc + gID) * PADH + k0 + 2 * tig);
            uint32_t b1 = *(const uint32_t*)(sW + (nc + gID) * PADH + k0 + 2 * tig + 8);
            mma_f16(acc[0][nf], a[0], b0, b1);
            mma_f16(acc[1][nf], a[1], b0, b1);
        }
    }

    if (!do_head) {
#pragma unroll
        for (int mf = 0; mf < 2; ++mf) {
            int r_lo = row0 + wm + mf * 16 + gID;
            int r_hi = r_lo + 8;
#pragma unroll
            for (int nf = 0; nf < 4; ++nf) {
                int col = wn + nf * 8 + tig * 2;
                float2 vlo = make_float2(acc[mf][nf][0], acc[mf][nf][1]);
                float2 vhi = make_float2(acc[mf][nf][2], acc[mf][nf][3]);
                if (has_bias) {
                    float bx = bias[col], by = bias[col + 1];
                    vlo.x += bx; vlo.y += by;
                    vhi.x += bx; vhi.y += by;
                }
                if (do_relu) {
                    vlo.x = fmaxf(vlo.x, 0.f); vlo.y = fmaxf(vlo.y, 0.f);
                    vhi.x = fmaxf(vhi.x, 0.f); vhi.y = fmaxf(vhi.y, 0.f);
                }
                if (r_lo < M) *(__half2*)(C16 + (size_t)r_lo * 128 + col) = __float22half2_rn(vlo);
                if (r_hi < M) *(__half2*)(C16 + (size_t)r_hi * 128 + col) = __float22half2_rn(vhi);
            }
        }
        return;
    }

    // ---- fused head path: 64-row tile -> smem fp32, then tile @ W2 + b2 ----
    __syncthreads();
    float* sT  = (float*)smh;               // [64][HPAD]
    float* sW2 = sT + 64 * HPAD;
    float* sb2 = sW2 + 128 * N_CLASSES;

#pragma unroll
    for (int mf = 0; mf < 2; ++mf) {
        int lr_lo = wm + mf * 16 + gID;
        int lr_hi = lr_lo + 8;
#pragma unroll
        for (int nf = 0; nf < 4; ++nf) {
            int col = wn + nf * 8 + tig * 2;
            float bx = bias[col], by = bias[col + 1];
            sT[lr_lo * HPAD + col]     = fmaxf(acc[mf][nf][0] + bx, 0.f);
            sT[lr_lo * HPAD + col + 1] = fmaxf(acc[mf][nf][1] + by, 0.f);
            sT[lr_hi * HPAD + col]     = fmaxf(acc[mf][nf][2] + bx, 0.f);
            sT[lr_hi * HPAD + col + 1] = fmaxf(acc[mf][nf][3] + by, 0.f);
        }
    }
    for (int i = tid; i < 128 * N_CLASSES; i += 256) sW2[i] = __ldg(W2 + i);
    if (tid < N_CLASSES) sb2[tid] = b2[tid];
    __syncthreads();

    // 640 outputs, 256 threads
    for (int o = tid; o < 64 * N_CLASSES; o += 256) {
        int r = o / N_CLASSES, c = o % N_CLASSES;
        int gr = row0 + r;
        if (gr >= M) continue;
        float s = sb2[c];
        const float* tr = sT + r * HPAD;
#pragma unroll
        for (int k = 0; k < 128; ++k)
            s = fmaf(tr[k], sW2[k * N_CLASSES + c], s);
        OutF[(size_t)gr * N_CLASSES + c] = s;
    }
}

// ---------------- CSR aggregation: one warp per node, 8-deep edge batch ----------------
__global__ __launch_bounds__(256) void k_aggregate(
    const __half* __restrict__ h, const float* __restrict__ bias,
    __half* __restrict__ out, int N)
{
    int warp = (blockIdx.x << 3) + (threadIdx.x >> 5);
    if (warp >= N) return;
    int i = warp;
    int lane = threadIdx.x & 31;

    const __half* hcol = h + lane * 4;
    float4 acc = make_float4(0.f, 0.f, 0.f, 0.f);

    int e0 = g_off[i], e1 = g_off[i + 1];
    for (int e = e0; e < e1; e += 8) {
        int n = e1 - e;
        int2 rec[8];
        uint2 hv[8];
#pragma unroll
        for (int j = 0; j < 8; ++j)
            if (j < n) rec[j] = __ldg(&g_edge[e + j]);
#pragma unroll
        for (int j = 0; j < 8; ++j)
            if (j < n) hv[j] = __ldg((const uint2*)(hcol + (size_t)rec[j].x * 128));
#pragma unroll
        for (int j = 0; j < 8; ++j) {
            if (j < n) {
                float nm = __int_as_float(rec[j].y);
                float2 a = __half22float2(*(const __half2*)&hv[j].x);
                float2 b = __half22float2(*(const __half2*)&hv[j].y);
                acc.x = fmaf(nm, a.x, acc.x); acc.y = fmaf(nm, a.y, acc.y);
                acc.z = fmaf(nm, b.x, acc.z); acc.w = fmaf(nm, b.y, acc.w);
            }
        }
    }

    float di = g_dinv[i];
    float dii = di * di;
    uint2 us = __ldg((const uint2*)(hcol + (size_t)i * 128));
    float2 sa = __half22float2(*(const __half2*)&us.x);
    float2 sb = __half22float2(*(const __half2*)&us.y);
    float4 bv = __ldg((const float4*)(bias + lane * 4));
    acc.x = fmaxf(fmaf(dii, sa.x, acc.x) + bv.x, 0.f);
    acc.y = fmaxf(fmaf(dii, sa.y, acc.y) + bv.y, 0.f);
    acc.z = fmaxf(fmaf(dii, sb.x, acc.z) + bv.z, 0.f);
    acc.w = fmaxf(fmaf(dii, sb.y, acc.w) + bv.w, 0.f);

    __half2 lo = __float22half2_rn(make_float2(acc.x, acc.y));
    __half2 hi = __float22half2_rn(make_float2(acc.z, acc.w));
    *(uint2*)(out + (size_t)i * 128 + lane * 4) =
        make_uint2(*(uint32_t*)&lo, *(uint32_t*)&hi);
}

// ---------------- host launch ----------------
extern "C" void kernel_launch(void* const* d_in, const int* in_sizes, int n_in,
                              void* d_out, int out_size)
{
    const float* x   = (const float*)d_in[0];
    const int*   ei  = (const int*)d_in[1];
    const float* W1  = (const float*)d_in[2];
    const float* b1  = (const float*)d_in[3];
    const float* W2  = (const float*)d_in[4];
    const float* b2  = (const float*)d_in[5];
    const float* W3  = (const float*)d_in[6];
    const float* b3  = (const float*)d_in[7];
    const float* fW1 = (const float*)d_in[8];
    const float* fb1 = (const float*)d_in[9];
    const float* fW2 = (const float*)d_in[10];
    const float* fb2 = (const float*)d_in[11];
    float* out = (float*)d_out;

    int N = in_sizes[0] / DIM;
    int E = in_sizes[1] / 2;
    const int* src = ei;
    const int* dst = ei + E;

    __half *bufH, *bufP, *wt;
    int* cntp;
    cudaGetSymbolAddress((void**)&bufH, g_bufH);
    cudaGetSymbolAddress((void**)&bufP, g_bufP);
    cudaGetSymbolAddress((void**)&wt,   g_Wt);
    cudaGetSymbolAddress((void**)&cntp, g_cnt);
    __half* Wt1 = wt;
    __half* Wt2 = wt + DIM * DIM;
    __half* Wt3 = wt + 2 * DIM * DIM;
    __half* Wt4 = wt + 3 * DIM * DIM;

    cudaFuncSetAttribute(k_gemm_mma, cudaFuncAttributeMaxDynamicSharedMemorySize,
                         (int)SMEM_BYTES);

    int nb256_E = (E + 255) / 256;
    int nbScan  = (N + SCAN_BS - 1) / SCAN_BS;
    int nbGemm  = (N + 63) / 64;
    int nbAgg   = (N + 7) / 8;

    // graph structure prep
    cudaMemsetAsync(cntp, 0, (size_t)N * sizeof(int));
    k_count_deg<<<nb256_E, 256>>>(dst, E);
    k_scan1<<<nbScan, SCAN_BS>>>(N);
    k_scan2<<<1, 128>>>(nbScan);
    k_scan3<<<nbScan, SCAN_BS>>>(N);
    k_scatter<<<nb256_E, 256>>>(src, dst, E);

    // weight pre-transpose (fp16), single launch for all 4
    dim3 trGrid(4, 4, 4), trBlk(32, 8);
    k_transW<<<trGrid, trBlk>>>(W1, W2, W3, fW1);

    // layer 1 (A from fp32 x, converted in staging)
    k_gemm_mma<<<nbGemm, 256, SMEM_BYTES>>>(nullptr, x, Wt1, nullptr, bufH,
                                            nullptr, nullptr, nullptr, N, 0, 0, 0);
    k_aggregate<<<nbAgg, 256>>>(bufH, b1, bufP, N);
    // layer 2
    k_gemm_mma<<<nbGemm, 256, SMEM_BYTES>>>(bufP, nullptr, Wt2, nullptr, bufH,
                                            nullptr, nullptr, nullptr, N, 0, 0, 0);
    k_aggregate<<<nbAgg, 256>>>(bufH, b2, bufP, N);
    // layer 3
    k_gemm_mma<<<nbGemm, 256, SMEM_BYTES>>>(bufP, nullptr, Wt3, nullptr, bufH,
                                            nullptr, nullptr, nullptr, N, 0, 0, 0);
    k_aggregate<<<nbAgg, 256>>>(bufH, b3, bufP, N);
    // FFN + fused head
    k_gemm_mma<<<nbGemm, 256, SMEM_BYTES>>>(bufP, nullptr, Wt4, fb1, nullptr,
                                            fW2, fb2, out, N, 1, 1, 1);
}

// round 13
// speedup vs baseline: 1.0407x; 1.0407x over previous
#include <cuda_runtime.h>
#include <cuda_fp16.h>
#include <cstdint>
#include <cstddef>

#define N_NODES   100000
#define N_EDGES   1600000
#define DIM       128
#define N_CLASSES 10

#define SCAN_BS   1024
#define SCAN_NB   ((N_NODES + SCAN_BS - 1) / SCAN_BS)   // 98 (<=128)

// ---------------- scratch (static __device__, no allocation) ----------------
__device__ __half g_bufH[(size_t)N_NODES * DIM];   // GEMM out h (gather target)
__device__ __half g_bufP[(size_t)N_NODES * DIM];   // aggregate out (GEMM A input)
__device__ __half g_Wt[4][DIM * DIM];              // transposed fp16 weights [n][k]
__device__ float  g_dinv[N_NODES];
__device__ int    g_cnt[N_NODES];                  // real-edge in-degree
__device__ int    g_off[N_NODES + 1];
__device__ int    g_cur[N_NODES];
__device__ int2   g_edge[N_EDGES];                 // (src, norm bits)
__device__ int    g_bsum[SCAN_NB];
__device__ int    g_bpref[SCAN_NB];

// ---------------- prep kernels ----------------
__global__ void k_count_deg(const int* __restrict__ dst, int e) {
    int i = blockIdx.x * blockDim.x + threadIdx.x;
    if (i < e) atomicAdd(&g_cnt[dst[i]], 1);
}
// scan1 + dinv fused: per-block inclusive scan of cnt, dinv = rsqrt(cnt+1)
__global__ void k_scan1(int n) {
    __shared__ int sh[SCAN_BS];
    int i = blockIdx.x * SCAN_BS + threadIdx.x;
    int c = (i < n) ? g_cnt[i] : 0;
    if (i < n) g_dinv[i] = rsqrtf((float)(c + 1));
    sh[threadIdx.x] = c;
    __syncthreads();
    for (int ofs = 1; ofs < SCAN_BS; ofs <<= 1) {
        int t = (threadIdx.x >= ofs) ? sh[threadIdx.x - ofs] : 0;
        __syncthreads();
        sh[threadIdx.x] += t;
        __syncthreads();
    }
    if (i < n) g_cur[i] = sh[threadIdx.x];
    if (threadIdx.x == SCAN_BS - 1) g_bsum[blockIdx.x] = sh[SCAN_BS - 1];
}
// parallel exclusive scan of block sums (nb <= 128), one block of 128 threads
__global__ void k_scan2(int nb) {
    __shared__ int wsum[4];
    int t = threadIdx.x;
    int lane = t & 31, w = t >> 5;
    int v = (t < nb) ? g_bsum[t] : 0;
    int inc = v;
#pragma unroll
    for (int ofs = 1; ofs < 32; ofs <<= 1) {
        int u = __shfl_up_sync(0xFFFFFFFF, inc, ofs);
        if (lane >= ofs) inc += u;
    }
    if (lane == 31) wsum[w] = inc;
    __syncthreads();
    int woff = 0;
#pragma unroll
    for (int j = 0; j < 4; ++j) woff += (j < w) ? wsum[j] : 0;
    if (t < nb) g_bpref[t] = woff + inc - v;   // exclusive
}
__global__ void k_scan3(int n) {
    int i = blockIdx.x * SCAN_BS + threadIdx.x;
    if (i >= n) return;
    int inc = g_cur[i] + g_bpref[blockIdx.x];
    int ex = inc - g_cnt[i];
    g_off[i] = ex;
    g_cur[i] = ex;
    if (i == n - 1) g_off[n] = inc;
}
__global__ void k_scatter(const int* __restrict__ src, const int* __restrict__ dst, int e) {
    int i = blockIdx.x * blockDim.x + threadIdx.x;
    if (i >= e) return;
    int s = src[i], d = dst[i];
    int p = atomicAdd(&g_cur[d], 1);
    float nm = g_dinv[s] * g_dinv[d];
    g_edge[p] = make_int2(s, __float_as_int(nm));
}

// one launch transposes all 4 weights: Wt[z][n][k] = fp16(W_z[k][n])
__global__ void k_transW(const float* __restrict__ Wa, const float* __restrict__ Wb,
                         const float* __restrict__ Wc, const float* __restrict__ Wd) {
    __shared__ float tile[32][33];
    const float* W = (blockIdx.z == 0) ? Wa : (blockIdx.z == 1) ? Wb
                   : (blockIdx.z == 2) ? Wc : Wd;
    __half* Wt = g_Wt[blockIdx.z];
    int bn = blockIdx.x * 32, bk = blockIdx.y * 32;
    int tx = threadIdx.x, ty = threadIdx.y;          // 32 x 8
#pragma unroll
    for (int r = 0; r < 32; r += 8)
        tile[ty + r][tx] = W[(size_t)(bk + ty + r) * 128 + bn + tx];
    __syncthreads();
#pragma unroll
    for (int r = 0; r < 32; r += 8)
        Wt[(size_t)(bn + ty + r) * 128 + bk + tx] = __float2half_rn(tile[tx][ty + r]);
}

// ---------------- fp16 mma.sync GEMM (+ optional fused 10-class head) ----------------
#define PADH 136
#define HPAD 129
#define GEMM_SMEM_BYTES (2 * 128 * PADH * sizeof(__half))
#define HEAD_SMEM_BYTES ((128 * HPAD + 128 * N_CLASSES + N_CLASSES) * 4)
#define SMEM_BYTES (HEAD_SMEM_BYTES > GEMM_SMEM_BYTES ? HEAD_SMEM_BYTES : GEMM_SMEM_BYTES)

__device__ __forceinline__ void mma_f16(float c[4], const uint32_t a[4],
                                        uint32_t b0, uint32_t b1) {
    asm volatile(
        "mma.sync.aligned.m16n8k16.row.col.f32.f16.f16.f32 "
        "{%0,%1,%2,%3}, {%4,%5,%6,%7}, {%8,%9}, {%0,%1,%2,%3};"
        : "+f"(c[0]), "+f"(c[1]), "+f"(c[2]), "+f"(c[3])
        : "r"(a[0]), "r"(a[1]), "r"(a[2]), "r"(a[3]), "r"(b0), "r"(b1));
}

__global__ __launch_bounds__(256) void k_gemm_mma(
    const __half* __restrict__ A16, const float* __restrict__ A32,
    const __half* __restrict__ Wt, const float* __restrict__ bias,
    __half* __restrict__ C16,
    const float* __restrict__ W2, const float* __restrict__ b2,
    float* __restrict__ OutF,
    int M, int has_bias, int do_relu, int do_head)
{
    extern __shared__ __half smh[];
    __half* sA = smh;
    __half* sW = smh + 128 * PADH;

    int tid = threadIdx.x;
    int wid = tid >> 5, lane = tid & 31;
    int gID = lane >> 2, tig = lane & 3;
    int row0 = blockIdx.x * 128;

    if (A32) {
#pragma unroll
        for (int i = 0; i < 16; ++i) {
            int fid = i * 256 + tid;
            int r = fid >> 5, c4 = (fid & 31) << 2;
            float4 v = make_float4(0.f, 0.f, 0.f, 0.f);
            int gr = row0 + r;
            if (gr < M) v = __ldg((const float4*)(A32 + (size_t)gr * 128 + c4));
            __half2 lo = __float22half2_rn(make_float2(v.x, v.y));
            __half2 hi = __float22half2_rn(make_float2(v.z, v.w));
            *(uint2*)(sA + r * PADH + c4) = make_uint2(*(uint32_t*)&lo, *(uint32_t*)&hi);
        }
    } else {
#pragma unroll
        for (int i = 0; i < 8; ++i) {
            int fid = i * 256 + tid;
            int r = fid >> 4, c8 = (fid & 15) << 3;
            uint4 v = make_uint4(0, 0, 0, 0);
            int gr = row0 + r;
            if (gr < M) v = __ldg((const uint4*)(A16 + (size_t)gr * 128 + c8));
            *(uint4*)(sA + r * PADH + c8) = v;
        }
    }
#pragma unroll
    for (int i = 0; i < 8; ++i) {
        int fid = i * 256 + tid;
        int n = fid >> 4, k8 = (fid & 15) << 3;
        uint4 v = __ldg((const uint4*)(Wt + (size_t)n * 128 + k8));
        *(uint4*)(sW + n * PADH + k8) = v;
    }
    __syncthreads();

    int wm = (wid & 3) * 32;
    int wn = (wid >> 2) * 64;

    float acc[2][8][4];
#pragma unroll
    for (int mf = 0; mf < 2; ++mf)
#pragma unroll
        for (int nf = 0; nf < 8; ++nf)
#pragma unroll
            for (int j = 0; j < 4; ++j) acc[mf][nf][j] = 0.f;

#pragma unroll
    for (int k0 = 0; k0 < 128; k0 += 16) {
        uint32_t a[2][4];
#pragma unroll
        for (int mf = 0; mf < 2; ++mf) {
            int mr = wm + mf * 16;
            a[mf][0] = *(const uint32_t*)(sA + (mr + gID)     * PADH + k0 + 2 * tig);
            a[mf][1] = *(const uint32_t*)(sA + (mr + gID + 8) * PADH + k0 + 2 * tig);
            a[mf][2] = *(const uint32_t*)(sA + (mr + gID)     * PADH + k0 + 2 * tig + 8);
            a[mf][3] = *(const uint32_t*)(sA + (mr + gID + 8) * PADH + k0 + 2 * tig + 8);
        }
#pragma unroll
        for (int nf = 0; nf < 8; ++nf) {
            int nc = wn + nf * 8;
            uint32_t b0 = *(const uint32_t*)(sW + (nc + gID) * PADH + k0 + 2 * tig);
            uint32_t b1 = *(const uint32_t*)(sW + (nc + gID) * PADH + k0 + 2 * tig + 8);
            mma_f16(acc[0][nf], a[0], b0, b1);
            mma_f16(acc[1][nf], a[1], b0, b1);
        }
    }

    if (!do_head) {
#pragma unroll
        for (int mf = 0; mf < 2; ++mf) {
            int r_lo = row0 + wm + mf * 16 + gID;
            int r_hi = r_lo + 8;
#pragma unroll
            for (int nf = 0; nf < 8; ++nf) {
                int col = wn + nf * 8 + tig * 2;
                float2 vlo = make_float2(acc[mf][nf][0], acc[mf][nf][1]);
                float2 vhi = make_float2(acc[mf][nf][2], acc[mf][nf][3]);
                if (has_bias) {
                    float bx = bias[col], by = bias[col + 1];
                    vlo.x += bx; vlo.y += by;
                    vhi.x += bx; vhi.y += by;
                }
                if (do_relu) {
                    vlo.x = fmaxf(vlo.x, 0.f); vlo.y = fmaxf(vlo.y, 0.f);
                    vhi.x = fmaxf(vhi.x, 0.f); vhi.y = fmaxf(vhi.y, 0.f);
                }
                if (r_lo < M) *(__half2*)(C16 + (size_t)r_lo * 128 + col) = __float22half2_rn(vlo);
                if (r_hi < M) *(__half2*)(C16 + (size_t)r_hi * 128 + col) = __float22half2_rn(vhi);
            }
        }
        return;
    }

    // ---- fused head path ----
    __syncthreads();
    float* sT  = (float*)smh;               // [128][HPAD]
    float* sW2 = sT + 128 * HPAD;
    float* sb2 = sW2 + 128 * N_CLASSES;

#pragma unroll
    for (int mf = 0; mf < 2; ++mf) {
        int lr_lo = wm + mf * 16 + gID;
        int lr_hi = lr_lo + 8;
#pragma unroll
        for (int nf = 0; nf < 8; ++nf) {
            int col = wn + nf * 8 + tig * 2;
            float bx = bias[col], by = bias[col + 1];
            sT[lr_lo * HPAD + col]     = fmaxf(acc[mf][nf][0] + bx, 0.f);
            sT[lr_lo * HPAD + col + 1] = fmaxf(acc[mf][nf][1] + by, 0.f);
            sT[lr_hi * HPAD + col]     = fmaxf(acc[mf][nf][2] + bx, 0.f);
            sT[lr_hi * HPAD + col + 1] = fmaxf(acc[mf][nf][3] + by, 0.f);
        }
    }
    for (int i = tid; i < 128 * N_CLASSES; i += 256) sW2[i] = __ldg(W2 + i);
    if (tid < N_CLASSES) sb2[tid] = b2[tid];
    __syncthreads();

    for (int o = tid; o < 128 * N_CLASSES; o += 256) {
        int r = o / N_CLASSES, c = o % N_CLASSES;
        int gr = row0 + r;
        if (gr >= M) continue;
        float s = sb2[c];
        const float* tr = sT + r * HPAD;
#pragma unroll
        for (int k = 0; k < 128; ++k)
            s = fmaf(tr[k], sW2[k * N_CLASSES + c], s);
        OutF[(size_t)gr * N_CLASSES + c] = s;
    }
}

// ---------------- CSR aggregation: one warp per node, 8-deep edge batch ----------------
__global__ __launch_bounds__(256) void k_aggregate(
    const __half* __restrict__ h, const float* __restrict__ bias,
    __half* __restrict__ out, int N)
{
    int warp = (blockIdx.x << 3) + (threadIdx.x >> 5);
    if (warp >= N) return;
    int i = warp;
    int lane = threadIdx.x & 31;

    const __half* hcol = h + lane * 4;
    float4 acc = make_float4(0.f, 0.f, 0.f, 0.f);

    int e0 = g_off[i], e1 = g_off[i + 1];
    for (int e = e0; e < e1; e += 8) {
        int n = e1 - e;
        int2 rec[8];
        uint2 hv[8];
#pragma unroll
        for (int j = 0; j < 8; ++j)
            if (j < n) rec[j] = __ldg(&g_edge[e + j]);
#pragma unroll
        for (int j = 0; j < 8; ++j)
            if (j < n) hv[j] = __ldg((const uint2*)(hcol + (size_t)rec[j].x * 128));
#pragma unroll
        for (int j = 0; j < 8; ++j) {
            if (j < n) {
                float nm = __int_as_float(rec[j].y);
                float2 a = __half22float2(*(const __half2*)&hv[j].x);
                float2 b = __half22float2(*(const __half2*)&hv[j].y);
                acc.x = fmaf(nm, a.x, acc.x); acc.y = fmaf(nm, a.y, acc.y);
                acc.z = fmaf(nm, b.x, acc.z); acc.w = fmaf(nm, b.y, acc.w);
            }
        }
    }

    float di = g_dinv[i];
    float dii = di * di;
    uint2 us = __ldg((const uint2*)(hcol + (size_t)i * 128));
    float2 sa = __half22float2(*(const __half2*)&us.x);
    float2 sb = __half22float2(*(const __half2*)&us.y);
    float4 bv = __ldg((const float4*)(bias + lane * 4));
    acc.x = fmaxf(fmaf(dii, sa.x, acc.x) + bv.x, 0.f);
    acc.y = fmaxf(fmaf(dii, sa.y, acc.y) + bv.y, 0.f);
    acc.z = fmaxf(fmaf(dii, sb.x, acc.z) + bv.z, 0.f);
    acc.w = fmaxf(fmaf(dii, sb.y, acc.w) + bv.w, 0.f);

    __half2 lo = __float22half2_rn(make_float2(acc.x, acc.y));
    __half2 hi = __float22half2_rn(make_float2(acc.z, acc.w));
    *(uint2*)(out + (size_t)i * 128 + lane * 4) =
        make_uint2(*(uint32_t*)&lo, *(uint32_t*)&hi);
}

// ---------------- host launch ----------------
extern "C" void kernel_launch(void* const* d_in, const int* in_sizes, int n_in,
                              void* d_out, int out_size)
{
    const float* x   = (const float*)d_in[0];
    const int*   ei  = (const int*)d_in[1];
    const float* W1  = (const float*)d_in[2];
    const float* b1  = (const float*)d_in[3];
    const float* W2  = (const float*)d_in[4];
    const float* b2  = (const float*)d_in[5];
    const float* W3  = (const float*)d_in[6];
    const float* b3  = (const float*)d_in[7];
    const float* fW1 = (const float*)d_in[8];
    const float* fb1 = (const float*)d_in[9];
    const float* fW2 = (const float*)d_in[10];
    const float* fb2 = (const float*)d_in[11];
    float* out = (float*)d_out;

    int N = in_sizes[0] / DIM;
    int E = in_sizes[1] / 2;
    const int* src = ei;
    const int* dst = ei + E;

    __half *bufH, *bufP, *wt;
    int* cntp;
    cudaGetSymbolAddress((void**)&bufH, g_bufH);
    cudaGetSymbolAddress((void**)&bufP, g_bufP);
    cudaGetSymbolAddress((void**)&wt,   g_Wt);
    cudaGetSymbolAddress((void**)&cntp, g_cnt);
    __half* Wt1 = wt;
    __half* Wt2 = wt + DIM * DIM;
    __half* Wt3 = wt + 2 * DIM * DIM;
    __half* Wt4 = wt + 3 * DIM * DIM;

    cudaFuncSetAttribute(k_gemm_mma, cudaFuncAttributeMaxDynamicSharedMemorySize,
                         (int)SMEM_BYTES);

    int nb256_E = (E + 255) / 256;
    int nbScan  = (N + SCAN_BS - 1) / SCAN_BS;
    int nbGemm  = (N + 127) / 128;
    int nbAgg   = (N + 7) / 8;

    // fork/join: graph prep on side stream, transW+GEMM1 on main stream
    cudaStream_t s2;
    cudaEvent_t evF, evJ;
    cudaStreamCreateWithFlags(&s2, cudaStreamNonBlocking);
    cudaEventCreateWithFlags(&evF, cudaEventDisableTiming);
    cudaEventCreateWithFlags(&evJ, cudaEventDisableTiming);

    cudaMemsetAsync(cntp, 0, (size_t)N * sizeof(int));
    cudaEventRecord(evF, 0);
    cudaStreamWaitEvent(s2, evF, 0);

    // side stream: graph structure prep
    k_count_deg<<<nb256_E, 256, 0, s2>>>(dst, E);
    k_scan1<<<nbScan, SCAN_BS, 0, s2>>>(N);
    k_scan2<<<1, 128, 0, s2>>>(nbScan);
    k_scan3<<<nbScan, SCAN_BS, 0, s2>>>(N);
    k_scatter<<<nb256_E, 256, 0, s2>>>(src, dst, E);
    cudaEventRecord(evJ, s2);

    // main stream: weight transpose + layer-1 GEMM (independent of prep)
    dim3 trGrid(4, 4, 4), trBlk(32, 8);
    k_transW<<<trGrid, trBlk>>>(W1, W2, W3, fW1);
    k_gemm_mma<<<nbGemm, 256, SMEM_BYTES>>>(nullptr, x, Wt1, nullptr, bufH,
                                            nullptr, nullptr, nullptr, N, 0, 0, 0);

    // join: aggregation needs both GEMM1 output and CSR
    cudaStreamWaitEvent(0, evJ, 0);
    k_aggregate<<<nbAgg, 256>>>(bufH, b1, bufP, N);
    // layer 2
    k_gemm_mma<<<nbGemm, 256, SMEM_BYTES>>>(bufP, nullptr, Wt2, nullptr, bufH,
                                            nullptr, nullptr, nullptr, N, 0, 0, 0);
    k_aggregate<<<nbAgg, 256>>>(bufH, b2, bufP, N);
    // layer 3
    k_gemm_mma<<<nbGemm, 256, SMEM_BYTES>>>(bufP, nullptr, Wt3, nullptr, bufH,
                                            nullptr, nullptr, nullptr, N, 0, 0, 0);
    k_aggregate<<<nbAgg, 256>>>(bufH, b3, bufP, N);
    // FFN + fused head
    k_gemm_mma<<<nbGemm, 256, SMEM_BYTES>>>(bufP, nullptr, Wt4, fb1, nullptr,
                                            fW2, fb2, out, N, 1, 1, 1);

    cudaEventDestroy(evF);
    cudaEventDestroy(evJ);
    cudaStreamDestroy(s2);
}

// round 14
// speedup vs baseline: 1.1539x; 1.1088x over previous
#include <cuda_runtime.h>
#include <cuda_fp16.h>
#include <cstdint>
#include <cstddef>

#define N_NODES   100000
#define N_EDGES   1600000
#define DIM       128
#define N_CLASSES 10

#define SCAN_BS   1024
#define SCAN_NB   ((N_NODES + SCAN_BS - 1) / SCAN_BS)   // 98 (<=128)

// ---------------- scratch (static __device__, no allocation) ----------------
__device__ __half g_bufH[(size_t)N_NODES * DIM];   // GEMM out h (gather target)
__device__ __half g_bufP[(size_t)N_NODES * DIM];   // aggregate out (GEMM A input)
__device__ __half g_Wt[4][DIM * DIM];              // transposed fp16 weights [n][k]
__device__ float  g_dinv[N_NODES];
__device__ int    g_cnt[N_NODES];                  // real-edge in-degree
__device__ int    g_off[N_NODES + 1];
__device__ int    g_cur[N_NODES];
__device__ int2   g_edge[N_EDGES];                 // (src, norm bits)
__device__ int    g_bsum[SCAN_NB];
__device__ int    g_bpref[SCAN_NB];

// ---------------- prep kernels ----------------
__global__ void k_count_deg(const int* __restrict__ dst, int e) {
    int i = blockIdx.x * blockDim.x + threadIdx.x;
    if (i < e) atomicAdd(&g_cnt[dst[i]], 1);
}
// scan1 + dinv fused: per-block inclusive scan of cnt, dinv = rsqrt(cnt+1)
__global__ void k_scan1(int n) {
    __shared__ int sh[SCAN_BS];
    int i = blockIdx.x * SCAN_BS + threadIdx.x;
    int c = (i < n) ? g_cnt[i] : 0;
    if (i < n) g_dinv[i] = rsqrtf((float)(c + 1));
    sh[threadIdx.x] = c;
    __syncthreads();
    for (int ofs = 1; ofs < SCAN_BS; ofs <<= 1) {
        int t = (threadIdx.x >= ofs) ? sh[threadIdx.x - ofs] : 0;
        __syncthreads();
        sh[threadIdx.x] += t;
        __syncthreads();
    }
    if (i < n) g_cur[i] = sh[threadIdx.x];
    if (threadIdx.x == SCAN_BS - 1) g_bsum[blockIdx.x] = sh[SCAN_BS - 1];
}
// parallel exclusive scan of block sums (nb <= 128), one block of 128 threads
__global__ void k_scan2(int nb) {
    __shared__ int wsum[4];
    int t = threadIdx.x;
    int lane = t & 31, w = t >> 5;
    int v = (t < nb) ? g_bsum[t] : 0;
    int inc = v;
#pragma unroll
    for (int ofs = 1; ofs < 32; ofs <<= 1) {
        int u = __shfl_up_sync(0xFFFFFFFF, inc, ofs);
        if (lane >= ofs) inc += u;
    }
    if (lane == 31) wsum[w] = inc;
    __syncthreads();
    int woff = 0;
#pragma unroll
    for (int j = 0; j < 4; ++j) woff += (j < w) ? wsum[j] : 0;
    if (t < nb) g_bpref[t] = woff + inc - v;   // exclusive
}
__global__ void k_scan3(int n) {
    int i = blockIdx.x * SCAN_BS + threadIdx.x;
    if (i >= n) return;
    int inc = g_cur[i] + g_bpref[blockIdx.x];
    int ex = inc - g_cnt[i];
    g_off[i] = ex;
    g_cur[i] = ex;
    if (i == n - 1) g_off[n] = inc;
}
__global__ void k_scatter(const int* __restrict__ src, const int* __restrict__ dst, int e) {
    int i = blockIdx.x * blockDim.x + threadIdx.x;
    if (i >= e) return;
    int s = src[i], d = dst[i];
    int p = atomicAdd(&g_cur[d], 1);
    float nm = g_dinv[s] * g_dinv[d];
    g_edge[p] = make_int2(s, __float_as_int(nm));
}

// one launch transposes all 4 weights: Wt[z][n][k] = fp16(W_z[k][n])
__global__ void k_transW(const float* __restrict__ Wa, const float* __restrict__ Wb,
                         const float* __restrict__ Wc, const float* __restrict__ Wd) {
    __shared__ float tile[32][33];
    const float* W = (blockIdx.z == 0) ? Wa : (blockIdx.z == 1) ? Wb
                   : (blockIdx.z == 2) ? Wc : Wd;
    __half* Wt = g_Wt[blockIdx.z];
    int bn = blockIdx.x * 32, bk = blockIdx.y * 32;
    int tx = threadIdx.x, ty = threadIdx.y;          // 32 x 8
#pragma unroll
    for (int r = 0; r < 32; r += 8)
        tile[ty + r][tx] = W[(size_t)(bk + ty + r) * 128 + bn + tx];
    __syncthreads();
#pragma unroll
    for (int r = 0; r < 32; r += 8)
        Wt[(size_t)(bn + ty + r) * 128 + bk + tx] = __float2half_rn(tile[tx][ty + r]);
}

// ---------------- fp16 mma.sync GEMM (+ optional fused 10-class head) ----------------
#define PADH 136
#define HPAD 129
#define GEMM_SMEM_BYTES (2 * 128 * PADH * sizeof(__half))
#define HEAD_SMEM_BYTES ((128 * HPAD + 128 * N_CLASSES + N_CLASSES) * 4)
#define SMEM_BYTES (HEAD_SMEM_BYTES > GEMM_SMEM_BYTES ? HEAD_SMEM_BYTES : GEMM_SMEM_BYTES)

__device__ __forceinline__ void mma_f16(float c[4], const uint32_t a[4],
                                        uint32_t b0, uint32_t b1) {
    asm volatile(
        "mma.sync.aligned.m16n8k16.row.col.f32.f16.f16.f32 "
        "{%0,%1,%2,%3}, {%4,%5,%6,%7}, {%8,%9}, {%0,%1,%2,%3};"
        : "+f"(c[0]), "+f"(c[1]), "+f"(c[2]), "+f"(c[3])
        : "r"(a[0]), "r"(a[1]), "r"(a[2]), "r"(a[3]), "r"(b0), "r"(b1));
}

__global__ __launch_bounds__(256) void k_gemm_mma(
    const __half* __restrict__ A16, const float* __restrict__ A32,
    const __half* __restrict__ Wt, const float* __restrict__ bias,
    __half* __restrict__ C16,
    const float* __restrict__ W2, const float* __restrict__ b2,
    float* __restrict__ OutF,
    int M, int has_bias, int do_relu, int do_head)
{
    extern __shared__ __half smh[];
    __half* sA = smh;
    __half* sW = smh + 128 * PADH;

    int tid = threadIdx.x;
    int wid = tid >> 5, lane = tid & 31;
    int gID = lane >> 2, tig = lane & 3;
    int row0 = blockIdx.x * 128;

    if (A32) {
#pragma unroll
        for (int i = 0; i < 16; ++i) {
            int fid = i * 256 + tid;
            int r = fid >> 5, c4 = (fid & 31) << 2;
            float4 v = make_float4(0.f, 0.f, 0.f, 0.f);
            int gr = row0 + r;
            if (gr < M) v = __ldg((const float4*)(A32 + (size_t)gr * 128 + c4));
            __half2 lo = __float22half2_rn(make_float2(v.x, v.y));
            __half2 hi = __float22half2_rn(make_float2(v.z, v.w));
            *(uint2*)(sA + r * PADH + c4) = make_uint2(*(uint32_t*)&lo, *(uint32_t*)&hi);
        }
    } else {
#pragma unroll
        for (int i = 0; i < 8; ++i) {
            int fid = i * 256 + tid;
            int r = fid >> 4, c8 = (fid & 15) << 3;
            uint4 v = make_uint4(0, 0, 0, 0);
            int gr = row0 + r;
            if (gr < M) v = __ldg((const uint4*)(A16 + (size_t)gr * 128 + c8));
            *(uint4*)(sA + r * PADH + c8) = v;
        }
    }
#pragma unroll
    for (int i = 0; i < 8; ++i) {
        int fid = i * 256 + tid;
        int n = fid >> 4, k8 = (fid & 15) << 3;
        uint4 v = __ldg((const uint4*)(Wt + (size_t)n * 128 + k8));
        *(uint4*)(sW + n * PADH + k8) = v;
    }
    __syncthreads();

    int wm = (wid & 3) * 32;
    int wn = (wid >> 2) * 64;

    float acc[2][8][4];
#pragma unroll
    for (int mf = 0; mf < 2; ++mf)
#pragma unroll
        for (int nf = 0; nf < 8; ++nf)
#pragma unroll
            for (int j = 0; j < 4; ++j) acc[mf][nf][j] = 0.f;

#pragma unroll
    for (int k0 = 0; k0 < 128; k0 += 16) {
        uint32_t a[2][4];
#pragma unroll
        for (int mf = 0; mf < 2; ++mf) {
            int mr = wm + mf * 16;
            a[mf][0] = *(const uint32_t*)(sA + (mr + gID)     * PADH + k0 + 2 * tig);
            a[mf][1] = *(const uint32_t*)(sA + (mr + gID + 8) * PADH + k0 + 2 * tig);
            a[mf][2] = *(const uint32_t*)(sA + (mr + gID)     * PADH + k0 + 2 * tig + 8);
            a[mf][3] = *(const uint32_t*)(sA + (mr + gID + 8) * PADH + k0 + 2 * tig + 8);
        }
#pragma unroll
        for (int nf = 0; nf < 8; ++nf) {
            int nc = wn + nf * 8;
            uint32_t b0 = *(const uint32_t*)(sW + (nc + gID) * PADH + k0 + 2 * tig);
            uint32_t b1 = *(const uint32_t*)(sW + (nc + gID) * PADH + k0 + 2 * tig + 8);
            mma_f16(acc[0][nf], a[0], b0, b1);
            mma_f16(acc[1][nf], a[1], b0, b1);
        }
    }

    if (!do_head) {
#pragma unroll
        for (int mf = 0; mf < 2; ++mf) {
            int r_lo = row0 + wm + mf * 16 + gID;
            int r_hi = r_lo + 8;
#pragma unroll
            for (int nf = 0; nf < 8; ++nf) {
                int col = wn + nf * 8 + tig * 2;
                float2 vlo = make_float2(acc[mf][nf][0], acc[mf][nf][1]);
                float2 vhi = make_float2(acc[mf][nf][2], acc[mf][nf][3]);
                if (has_bias) {
                    float bx = bias[col], by = bias[col + 1];
                    vlo.x += bx; vlo.y += by;
                    vhi.x += bx; vhi.y += by;
                }
                if (do_relu) {
                    vlo.x = fmaxf(vlo.x, 0.f); vlo.y = fmaxf(vlo.y, 0.f);
                    vhi.x = fmaxf(vhi.x, 0.f); vhi.y = fmaxf(vhi.y, 0.f);
                }
                if (r_lo < M) *(__half2*)(C16 + (size_t)r_lo * 128 + col) = __float22half2_rn(vlo);
                if (r_hi < M) *(__half2*)(C16 + (size_t)r_hi * 128 + col) = __float22half2_rn(vhi);
            }
        }
        return;
    }

    // ---- fused head path ----
    __syncthreads();
    float* sT  = (float*)smh;               // [128][HPAD]
    float* sW2 = sT + 128 * HPAD;
    float* sb2 = sW2 + 128 * N_CLASSES;

#pragma unroll
    for (int mf = 0; mf < 2; ++mf) {
        int lr_lo = wm + mf * 16 + gID;
        int lr_hi = lr_lo + 8;
#pragma unroll
        for (int nf = 0; nf < 8; ++nf) {
            int col = wn + nf * 8 + tig * 2;
            float bx = bias[col], by = bias[col + 1];
            sT[lr_lo * HPAD + col]     = fmaxf(acc[mf][nf][0] + bx, 0.f);
            sT[lr_lo * HPAD + col + 1] = fmaxf(acc[mf][nf][1] + by, 0.f);
            sT[lr_hi * HPAD + col]     = fmaxf(acc[mf][nf][2] + bx, 0.f);
            sT[lr_hi * HPAD + col + 1] = fmaxf(acc[mf][nf][3] + by, 0.f);
        }
    }
    for (int i = tid; i < 128 * N_CLASSES; i += 256) sW2[i] = __ldg(W2 + i);
    if (tid < N_CLASSES) sb2[tid] = b2[tid];
    __syncthreads();

    for (int o = tid; o < 128 * N_CLASSES; o += 256) {
        int r = o / N_CLASSES, c = o % N_CLASSES;
        int gr = row0 + r;
        if (gr >= M) continue;
        float s = sb2[c];
        const float* tr = sT + r * HPAD;
#pragma unroll
        for (int k = 0; k < 128; ++k)
            s = fmaf(tr[k], sW2[k * N_CLASSES + c], s);
        OutF[(size_t)gr * N_CLASSES + c] = s;
    }
}

// ---------------- CSR aggregation: paired-edge LDG.128 ----------------
// 256 threads = 8 warps = 8 nodes/CTA. Lanes split: half = lane>>4 handles
// edges of that parity; sub = lane&15 owns 8 feature columns (16B).
// Per 8-edge batch: 4 rec LDGs + 4 uint4 gathers per lane (vs 8+8 LDG.64).
__global__ __launch_bounds__(256) void k_aggregate(
    const __half* __restrict__ h, const float* __restrict__ bias,
    __half* __restrict__ out, int N)
{
    int warp = (blockIdx.x << 3) + (threadIdx.x >> 5);
    if (warp >= N) return;
    int i = warp;
    int lane = threadIdx.x & 31;
    int sub = lane & 15, half = lane >> 4;

    const __half* hcol = h + sub * 8;
    float acc[8];
#pragma unroll
    for (int t = 0; t < 8; ++t) acc[t] = 0.f;

    int e0 = g_off[i], e1 = g_off[i + 1];
    for (int e = e0; e < e1; e += 8) {
        int2 rec[4];
        uint4 hv[4];
#pragma unroll
        for (int k = 0; k < 4; ++k) {
            int idx = e + 2 * k + half;
            if (idx < e1) rec[k] = __ldg(&g_edge[idx]);
        }
#pragma unroll
        for (int k = 0; k < 4; ++k) {
            int idx = e + 2 * k + half;
            if (idx < e1) hv[k] = __ldg((const uint4*)(hcol + (size_t)rec[k].x * 128));
        }
#pragma unroll
        for (int k = 0; k < 4; ++k) {
            int idx = e + 2 * k + half;
            if (idx < e1) {
                float nm = __int_as_float(rec[k].y);
                const __half2* p = (const __half2*)&hv[k];
#pragma unroll
                for (int t = 0; t < 4; ++t) {
                    float2 f = __half22float2(p[t]);
                    acc[2 * t]     = fmaf(nm, f.x, acc[2 * t]);
                    acc[2 * t + 1] = fmaf(nm, f.y, acc[2 * t + 1]);
                }
            }
        }
    }

    // merge the two edge-parity halves: lane L += lane L^16
#pragma unroll
    for (int t = 0; t < 8; ++t)
        acc[t] += __shfl_xor_sync(0xFFFFFFFF, acc[t], 16);

    if (half == 0) {
        float di = g_dinv[i];
        float dii = di * di;
        uint4 us = __ldg((const uint4*)(hcol + (size_t)i * 128));
        const __half2* sp = (const __half2*)&us;
        float4 bv0 = __ldg((const float4*)(bias + sub * 8));
        float4 bv1 = __ldg((const float4*)(bias + sub * 8 + 4));
        float bb[8] = {bv0.x, bv0.y, bv0.z, bv0.w, bv1.x, bv1.y, bv1.z, bv1.w};
        float res[8];
#pragma unroll
        for (int t = 0; t < 4; ++t) {
            float2 f = __half22float2(sp[t]);
            res[2 * t]     = fmaxf(fmaf(dii, f.x, acc[2 * t])     + bb[2 * t],     0.f);
            res[2 * t + 1] = fmaxf(fmaf(dii, f.y, acc[2 * t + 1]) + bb[2 * t + 1], 0.f);
        }
        uint4 ov;
        __half2 o0 = __float22half2_rn(make_float2(res[0], res[1]));
        __half2 o1 = __float22half2_rn(make_float2(res[2], res[3]));
        __half2 o2 = __float22half2_rn(make_float2(res[4], res[5]));
        __half2 o3 = __float22half2_rn(make_float2(res[6], res[7]));
        ov.x = *(uint32_t*)&o0; ov.y = *(uint32_t*)&o1;
        ov.z = *(uint32_t*)&o2; ov.w = *(uint32_t*)&o3;
        *(uint4*)(out + (size_t)i * 128 + sub * 8) = ov;
    }
}

// ---------------- host launch ----------------
extern "C" void kernel_launch(void* const* d_in, const int* in_sizes, int n_in,
                              void* d_out, int out_size)
{
    const float* x   = (const float*)d_in[0];
    const int*   ei  = (const int*)d_in[1];
    const float* W1  = (const float*)d_in[2];
    const float* b1  = (const float*)d_in[3];
    const float* W2  = (const float*)d_in[4];
    const float* b2  = (const float*)d_in[5];
    const float* W3  = (const float*)d_in[6];
    const float* b3  = (const float*)d_in[7];
    const float* fW1 = (const float*)d_in[8];
    const float* fb1 = (const float*)d_in[9];
    const float* fW2 = (const float*)d_in[10];
    const float* fb2 = (const float*)d_in[11];
    float* out = (float*)d_out;

    int N = in_sizes[0] / DIM;
    int E = in_sizes[1] / 2;
    const int* src = ei;
    const int* dst = ei + E;

    __half *bufH, *bufP, *wt;
    int* cntp;
    cudaGetSymbolAddress((void**)&bufH, g_bufH);
    cudaGetSymbolAddress((void**)&bufP, g_bufP);
    cudaGetSymbolAddress((void**)&wt,   g_Wt);
    cudaGetSymbolAddress((void**)&cntp, g_cnt);
    __half* Wt1 = wt;
    __half* Wt2 = wt + DIM * DIM;
    __half* Wt3 = wt + 2 * DIM * DIM;
    __half* Wt4 = wt + 3 * DIM * DIM;

    cudaFuncSetAttribute(k_gemm_mma, cudaFuncAttributeMaxDynamicSharedMemorySize,
                         (int)SMEM_BYTES);

    int nb256_E = (E + 255) / 256;
    int nbScan  = (N + SCAN_BS - 1) / SCAN_BS;
    int nbGemm  = (N + 127) / 128;
    int nbAgg   = (N + 7) / 8;

    // fork/join: graph prep on side stream, transW+GEMM1 on main stream
    cudaStream_t s2;
    cudaEvent_t evF, evJ;
    cudaStreamCreateWithFlags(&s2, cudaStreamNonBlocking);
    cudaEventCreateWithFlags(&evF, cudaEventDisableTiming);
    cudaEventCreateWithFlags(&evJ, cudaEventDisableTiming);

    cudaMemsetAsync(cntp, 0, (size_t)N * sizeof(int));
    cudaEventRecord(evF, 0);
    cudaStreamWaitEvent(s2, evF, 0);

    // side stream: graph structure prep
    k_count_deg<<<nb256_E, 256, 0, s2>>>(dst, E);
    k_scan1<<<nbScan, SCAN_BS, 0, s2>>>(N);
    k_scan2<<<1, 128, 0, s2>>>(nbScan);
    k_scan3<<<nbScan, SCAN_BS, 0, s2>>>(N);
    k_scatter<<<nb256_E, 256, 0, s2>>>(src, dst, E);
    cudaEventRecord(evJ, s2);

    // main stream: weight transpose + layer-1 GEMM (independent of prep)
    dim3 trGrid(4, 4, 4), trBlk(32, 8);
    k_transW<<<trGrid, trBlk>>>(W1, W2, W3, fW1);
    k_gemm_mma<<<nbGemm, 256, SMEM_BYTES>>>(nullptr, x, Wt1, nullptr, bufH,
                                            nullptr, nullptr, nullptr, N, 0, 0, 0);

    // join: aggregation needs both GEMM1 output and CSR
    cudaStreamWaitEvent(0, evJ, 0);
    k_aggregate<<<nbAgg, 256>>>(bufH, b1, bufP, N);
    // layer 2
    k_gemm_mma<<<nbGemm, 256, SMEM_BYTES>>>(bufP, nullptr, Wt2, nullptr, bufH,
                                            nullptr, nullptr, nullptr, N, 0, 0, 0);
    k_aggregate<<<nbAgg, 256>>>(bufH, b2, bufP, N);
    // layer 3
    k_gemm_mma<<<nbGemm, 256, SMEM_BYTES>>>(bufP, nullptr, Wt3, nullptr, bufH,
                                            nullptr, nullptr, nullptr, N, 0, 0, 0);
    k_aggregate<<<nbAgg, 256>>>(bufH, b3, bufP, N);
    // FFN + fused head
    k_gemm_mma<<<nbGemm, 256, SMEM_BYTES>>>(bufP, nullptr, Wt4, fb1, nullptr,
                                            fW2, fb2, out, N, 1, 1, 1);

    cudaEventDestroy(evF);
    cudaEventDestroy(evJ);
    cudaStreamDestroy(s2);
}

// round 15
// speedup vs baseline: 1.1557x; 1.0016x over previous
#include <cuda_runtime.h>
#include <cuda_fp16.h>
#include <cuda_pipeline.h>
#include <cstdint>
#include <cstddef>

#define N_NODES   100000
#define N_EDGES   1600000
#define DIM       128
#define N_CLASSES 10

#define SCAN_BS   1024
#define SCAN_NB   ((N_NODES + SCAN_BS - 1) / SCAN_BS)   // 98 (<=128)

// ---------------- scratch (static __device__, no allocation) ----------------
__device__ __half g_bufH[(size_t)N_NODES * DIM];   // GEMM out h (gather target)
__device__ __half g_bufP[(size_t)N_NODES * DIM];   // aggregate out (GEMM A input)
__device__ __half g_Wt[4][DIM * DIM];              // transposed fp16 weights [n][k]
__device__ float  g_dinv[N_NODES];
__device__ int    g_cnt[N_NODES];                  // real-edge in-degree
__device__ int    g_off[N_NODES + 1];
__device__ int    g_cur[N_NODES];
__device__ int2   g_edge[N_EDGES];                 // (src, norm bits)
__device__ int    g_bsum[SCAN_NB];
__device__ int    g_bpref[SCAN_NB];

// ---------------- prep kernels ----------------
__global__ void k_count_deg(const int* __restrict__ dst, int e) {
    int i = blockIdx.x * blockDim.x + threadIdx.x;
    if (i < e) atomicAdd(&g_cnt[dst[i]], 1);
}
__global__ void k_scan1(int n) {
    __shared__ int sh[SCAN_BS];
    int i = blockIdx.x * SCAN_BS + threadIdx.x;
    int c = (i < n) ? g_cnt[i] : 0;
    if (i < n) g_dinv[i] = rsqrtf((float)(c + 1));
    sh[threadIdx.x] = c;
    __syncthreads();
    for (int ofs = 1; ofs < SCAN_BS; ofs <<= 1) {
        int t = (threadIdx.x >= ofs) ? sh[threadIdx.x - ofs] : 0;
        __syncthreads();
        sh[threadIdx.x] += t;
        __syncthreads();
    }
    if (i < n) g_cur[i] = sh[threadIdx.x];
    if (threadIdx.x == SCAN_BS - 1) g_bsum[blockIdx.x] = sh[SCAN_BS - 1];
}
__global__ void k_scan2(int nb) {
    __shared__ int wsum[4];
    int t = threadIdx.x;
    int lane = t & 31, w = t >> 5;
    int v = (t < nb) ? g_bsum[t] : 0;
    int inc = v;
#pragma unroll
    for (int ofs = 1; ofs < 32; ofs <<= 1) {
        int u = __shfl_up_sync(0xFFFFFFFF, inc, ofs);
        if (lane >= ofs) inc += u;
    }
    if (lane == 31) wsum[w] = inc;
    __syncthreads();
    int woff = 0;
#pragma unroll
    for (int j = 0; j < 4; ++j) woff += (j < w) ? wsum[j] : 0;
    if (t < nb) g_bpref[t] = woff + inc - v;
}
__global__ void k_scan3(int n) {
    int i = blockIdx.x * SCAN_BS + threadIdx.x;
    if (i >= n) return;
    int inc = g_cur[i] + g_bpref[blockIdx.x];
    int ex = inc - g_cnt[i];
    g_off[i] = ex;
    g_cur[i] = ex;
    if (i == n - 1) g_off[n] = inc;
}
__global__ void k_scatter(const int* __restrict__ src, const int* __restrict__ dst, int e) {
    int i = blockIdx.x * blockDim.x + threadIdx.x;
    if (i >= e) return;
    int s = src[i], d = dst[i];
    int p = atomicAdd(&g_cur[d], 1);
    float nm = g_dinv[s] * g_dinv[d];
    g_edge[p] = make_int2(s, __float_as_int(nm));
}

__global__ void k_transW(const float* __restrict__ Wa, const float* __restrict__ Wb,
                         const float* __restrict__ Wc, const float* __restrict__ Wd) {
    __shared__ float tile[32][33];
    const float* W = (blockIdx.z == 0) ? Wa : (blockIdx.z == 1) ? Wb
                   : (blockIdx.z == 2) ? Wc : Wd;
    __half* Wt = g_Wt[blockIdx.z];
    int bn = blockIdx.x * 32, bk = blockIdx.y * 32;
    int tx = threadIdx.x, ty = threadIdx.y;
#pragma unroll
    for (int r = 0; r < 32; r += 8)
        tile[ty + r][tx] = W[(size_t)(bk + ty + r) * 128 + bn + tx];
    __syncthreads();
#pragma unroll
    for (int r = 0; r < 32; r += 8)
        Wt[(size_t)(bn + ty + r) * 128 + bk + tx] = __float2half_rn(tile[tx][ty + r]);
}

// ---------------- fp16 mma GEMM: persistent multi-tile, cp.async double-buffered A ----------------
#define PADH 136
#define HPAD 129
// smem layout (halves): [W: 128*PADH][A0: 128*PADH][A1: 128*PADH]
// head region overlays A0+A1 (byte offset 128*PADH*2 .. +71208)
#define SMEM_BYTES 106496

__device__ __forceinline__ void mma_f16(float c[4], const uint32_t a[4],
                                        uint32_t b0, uint32_t b1) {
    asm volatile(
        "mma.sync.aligned.m16n8k16.row.col.f32.f16.f16.f32 "
        "{%0,%1,%2,%3}, {%4,%5,%6,%7}, {%8,%9}, {%0,%1,%2,%3};"
        : "+f"(c[0]), "+f"(c[1]), "+f"(c[2]), "+f"(c[3])
        : "r"(a[0]), "r"(a[1]), "r"(a[2]), "r"(a[3]), "r"(b0), "r"(b1));
}

__device__ __forceinline__ void prefetchA16(__half* dst, const __half* A16,
                                            int t, int M, int tid) {
#pragma unroll
    for (int i = 0; i < 8; ++i) {
        int fid = i * 256 + tid;
        int r = fid >> 4, c8 = (fid & 15) << 3;
        int gr = t * 128 + r;
        __half* d = dst + r * PADH + c8;
        if (gr < M)
            __pipeline_memcpy_async(d, A16 + (size_t)gr * 128 + c8, 16);
        else
            *(uint4*)d = make_uint4(0, 0, 0, 0);
    }
}

__global__ __launch_bounds__(256) void k_gemm_mma(
    const __half* __restrict__ A16, const float* __restrict__ A32,
    const __half* __restrict__ Wt, const float* __restrict__ bias,
    __half* __restrict__ C16,
    const float* __restrict__ W2, const float* __restrict__ b2,
    float* __restrict__ OutF,
    int M, int has_bias, int do_relu, int do_head)
{
    extern __shared__ __half smh[];
    __half* sW  = smh;                      // [128][PADH]
    __half* sA0 = smh + 128 * PADH;
    __half* sA1 = smh + 2 * 128 * PADH;

    int tid = threadIdx.x;
    int wid = tid >> 5, lane = tid & 31;
    int gID = lane >> 2, tig = lane & 3;
    int nT = (M + 127) >> 7;

    // stage W once per CTA
#pragma unroll
    for (int i = 0; i < 8; ++i) {
        int fid = i * 256 + tid;
        int n = fid >> 4, k8 = (fid & 15) << 3;
        *(uint4*)(sW + n * PADH + k8) = __ldg((const uint4*)(Wt + (size_t)n * 128 + k8));
    }

    int wm = (wid & 3) * 32;
    int wn = (wid >> 2) * 64;

    bool pipelined = (A32 == nullptr) && !do_head;

    if (pipelined) {
        int t0 = blockIdx.x;
        if (t0 < nT) prefetchA16(sA0, A16, t0, M, tid);
        __pipeline_commit();
        int it = 0;
        for (int t = t0; t < nT; t += gridDim.x, ++it) {
            __half* cur = (it & 1) ? sA1 : sA0;
            __half* nxt = (it & 1) ? sA0 : sA1;
            __pipeline_wait_prior(0);
            __syncthreads();
            int tn = t + gridDim.x;
            if (tn < nT) prefetchA16(nxt, A16, tn, M, tid);
            __pipeline_commit();

            float acc[2][8][4];
#pragma unroll
            for (int mf = 0; mf < 2; ++mf)
#pragma unroll
                for (int nf = 0; nf < 8; ++nf)
#pragma unroll
                    for (int j = 0; j < 4; ++j) acc[mf][nf][j] = 0.f;

#pragma unroll
            for (int k0 = 0; k0 < 128; k0 += 16) {
                uint32_t a[2][4];
#pragma unroll
                for (int mf = 0; mf < 2; ++mf) {
                    int mr = wm + mf * 16;
                    a[mf][0] = *(const uint32_t*)(cur + (mr + gID)     * PADH + k0 + 2 * tig);
                    a[mf][1] = *(const uint32_t*)(cur + (mr + gID + 8) * PADH + k0 + 2 * tig);
                    a[mf][2] = *(const uint32_t*)(cur + (mr + gID)     * PADH + k0 + 2 * tig + 8);
                    a[mf][3] = *(const uint32_t*)(cur + (mr + gID + 8) * PADH + k0 + 2 * tig + 8);
                }
#pragma unroll
                for (int nf = 0; nf < 8; ++nf) {
                    int nc = wn + nf * 8;
                    uint32_t b0 = *(const uint32_t*)(sW + (nc + gID) * PADH + k0 + 2 * tig);
                    uint32_t b1 = *(const uint32_t*)(sW + (nc + gID) * PADH + k0 + 2 * tig + 8);
                    mma_f16(acc[0][nf], a[0], b0, b1);
                    mma_f16(acc[1][nf], a[1], b0, b1);
                }
            }

            int row0 = t * 128;
#pragma unroll
            for (int mf = 0; mf < 2; ++mf) {
                int r_lo = row0 + wm + mf * 16 + gID;
                int r_hi = r_lo + 8;
#pragma unroll
                for (int nf = 0; nf < 8; ++nf) {
                    int col = wn + nf * 8 + tig * 2;
                    float2 vlo = make_float2(acc[mf][nf][0], acc[mf][nf][1]);
                    float2 vhi = make_float2(acc[mf][nf][2], acc[mf][nf][3]);
                    if (r_lo < M) *(__half2*)(C16 + (size_t)r_lo * 128 + col) = __float22half2_rn(vlo);
                    if (r_hi < M) *(__half2*)(C16 + (size_t)r_hi * 128 + col) = __float22half2_rn(vhi);
                }
            }
        }
        return;
    }

    // unpipelined multi-tile loop (A32 convert path, and/or fused-head path)
    for (int t = blockIdx.x; t < nT; t += gridDim.x) {
        __syncthreads();   // protect sA0 / head-region reuse
        int row0 = t * 128;
        if (A32) {
#pragma unroll
            for (int i = 0; i < 16; ++i) {
                int fid = i * 256 + tid;
                int r = fid >> 5, c4 = (fid & 31) << 2;
                float4 v = make_float4(0.f, 0.f, 0.f, 0.f);
                int gr = row0 + r;
                if (gr < M) v = __ldg((const float4*)(A32 + (size_t)gr * 128 + c4));
                __half2 lo = __float22half2_rn(make_float2(v.x, v.y));
                __half2 hi = __float22half2_rn(make_float2(v.z, v.w));
                *(uint2*)(sA0 + r * PADH + c4) = make_uint2(*(uint32_t*)&lo, *(uint32_t*)&hi);
            }
        } else {
#pragma unroll
            for (int i = 0; i < 8; ++i) {
                int fid = i * 256 + tid;
                int r = fid >> 4, c8 = (fid & 15) << 3;
                uint4 v = make_uint4(0, 0, 0, 0);
                int gr = row0 + r;
                if (gr < M) v = __ldg((const uint4*)(A16 + (size_t)gr * 128 + c8));
                *(uint4*)(sA0 + r * PADH + c8) = v;
            }
        }
        __syncthreads();

        float acc[2][8][4];
#pragma unroll
        for (int mf = 0; mf < 2; ++mf)
#pragma unroll
            for (int nf = 0; nf < 8; ++nf)
#pragma unroll
                for (int j = 0; j < 4; ++j) acc[mf][nf][j] = 0.f;

#pragma unroll
        for (int k0 = 0; k0 < 128; k0 += 16) {
            uint32_t a[2][4];
#pragma unroll
            for (int mf = 0; mf < 2; ++mf) {
                int mr = wm + mf * 16;
                a[mf][0] = *(const uint32_t*)(sA0 + (mr + gID)     * PADH + k0 + 2 * tig);
                a[mf][1] = *(const uint32_t*)(sA0 + (mr + gID + 8) * PADH + k0 + 2 * tig);
                a[mf][2] = *(const uint32_t*)(sA0 + (mr + gID)     * PADH + k0 + 2 * tig + 8);
                a[mf][3] = *(const uint32_t*)(sA0 + (mr + gID + 8) * PADH + k0 + 2 * tig + 8);
            }
#pragma unroll
            for (int nf = 0; nf < 8; ++nf) {
                int nc = wn + nf * 8;
                uint32_t b0 = *(const uint32_t*)(sW + (nc + gID) * PADH + k0 + 2 * tig);
                uint32_t b1 = *(const uint32_t*)(sW + (nc + gID) * PADH + k0 + 2 * tig + 8);
                mma_f16(acc[0][nf], a[0], b0, b1);
                mma_f16(acc[1][nf], a[1], b0, b1);
            }
        }

        if (!do_head) {
#pragma unroll
            for (int mf = 0; mf < 2; ++mf) {
                int r_lo = row0 + wm + mf * 16 + gID;
                int r_hi = r_lo + 8;
#pragma unroll
                for (int nf = 0; nf < 8; ++nf) {
                    int col = wn + nf * 8 + tig * 2;
                    float2 vlo = make_float2(acc[mf][nf][0], acc[mf][nf][1]);
                    float2 vhi = make_float2(acc[mf][nf][2], acc[mf][nf][3]);
                    if (has_bias) {
                        float bx = bias[col], by = bias[col + 1];
                        vlo.x += bx; vlo.y += by;
                        vhi.x += bx; vhi.y += by;
                    }
                    if (do_relu) {
                        vlo.x = fmaxf(vlo.x, 0.f); vlo.y = fmaxf(vlo.y, 0.f);
                        vhi.x = fmaxf(vhi.x, 0.f); vhi.y = fmaxf(vhi.y, 0.f);
                    }
                    if (r_lo < M) *(__half2*)(C16 + (size_t)r_lo * 128 + col) = __float22half2_rn(vlo);
                    if (r_hi < M) *(__half2*)(C16 + (size_t)r_hi * 128 + col) = __float22half2_rn(vhi);
                }
            }
        } else {
            // fused head: tile -> smem fp32 (overlays A region, W preserved), then @ W2 + b2
            __syncthreads();
            float* sT  = (float*)(smh + 128 * PADH);    // [128][HPAD]
            float* sW2 = sT + 128 * HPAD;
            float* sb2 = sW2 + 128 * N_CLASSES;

#pragma unroll
            for (int mf = 0; mf < 2; ++mf) {
                int lr_lo = wm + mf * 16 + gID;
                int lr_hi = lr_lo + 8;
#pragma unroll
                for (int nf = 0; nf < 8; ++nf) {
                    int col = wn + nf * 8 + tig * 2;
                    float bx = bias[col], by = bias[col + 1];
                    sT[lr_lo * HPAD + col]     = fmaxf(acc[mf][nf][0] + bx, 0.f);
                    sT[lr_lo * HPAD + col + 1] = fmaxf(acc[mf][nf][1] + by, 0.f);
                    sT[lr_hi * HPAD + col]     = fmaxf(acc[mf][nf][2] + bx, 0.f);
                    sT[lr_hi * HPAD + col + 1] = fmaxf(acc[mf][nf][3] + by, 0.f);
                }
            }
            for (int i = tid; i < 128 * N_CLASSES; i += 256) sW2[i] = __ldg(W2 + i);
            if (tid < N_CLASSES) sb2[tid] = b2[tid];
            __syncthreads();

            for (int o = tid; o < 128 * N_CLASSES; o += 256) {
                int r = o / N_CLASSES, c = o % N_CLASSES;
                int gr = row0 + r;
                if (gr >= M) continue;
                float s = sb2[c];
                const float* tr = sT + r * HPAD;
#pragma unroll
                for (int k = 0; k < 128; ++k)
                    s = fmaf(tr[k], sW2[k * N_CLASSES + c], s);
                OutF[(size_t)gr * N_CLASSES + c] = s;
            }
        }
    }
}

// ---------------- CSR aggregation: paired-edge LDG.128 (R14 proven) ----------------
__global__ __launch_bounds__(256) void k_aggregate(
    const __half* __restrict__ h, const float* __restrict__ bias,
    __half* __restrict__ out, int N)
{
    int warp = (blockIdx.x << 3) + (threadIdx.x >> 5);
    if (warp >= N) return;
    int i = warp;
    int lane = threadIdx.x & 31;
    int sub = lane & 15, half = lane >> 4;

    const __half* hcol = h + sub * 8;
    float acc[8];
#pragma unroll
    for (int t = 0; t < 8; ++t) acc[t] = 0.f;

    int e0 = g_off[i], e1 = g_off[i + 1];
    for (int e = e0; e < e1; e += 8) {
        int2 rec[4];
        uint4 hv[4];
#pragma unroll
        for (int k = 0; k < 4; ++k) {
            int idx = e + 2 * k + half;
            if (idx < e1) rec[k] = __ldg(&g_edge[idx]);
        }
#pragma unroll
        for (int k = 0; k < 4; ++k) {
            int idx = e + 2 * k + half;
            if (idx < e1) hv[k] = __ldg((const uint4*)(hcol + (size_t)rec[k].x * 128));
        }
#pragma unroll
        for (int k = 0; k < 4; ++k) {
            int idx = e + 2 * k + half;
            if (idx < e1) {
                float nm = __int_as_float(rec[k].y);
                const __half2* p = (const __half2*)&hv[k];
#pragma unroll
                for (int t = 0; t < 4; ++t) {
                    float2 f = __half22float2(p[t]);
                    acc[2 * t]     = fmaf(nm, f.x, acc[2 * t]);
                    acc[2 * t + 1] = fmaf(nm, f.y, acc[2 * t + 1]);
                }
            }
        }
    }

#pragma unroll
    for (int t = 0; t < 8; ++t)
        acc[t] += __shfl_xor_sync(0xFFFFFFFF, acc[t], 16);

    if (half == 0) {
        float di = g_dinv[i];
        float dii = di * di;
        uint4 us = __ldg((const uint4*)(hcol + (size_t)i * 128));
        const __half2* sp = (const __half2*)&us;
        float4 bv0 = __ldg((const float4*)(bias + sub * 8));
        float4 bv1 = __ldg((const float4*)(bias + sub * 8 + 4));
        float bb[8] = {bv0.x, bv0.y, bv0.z, bv0.w, bv1.x, bv1.y, bv1.z, bv1.w};
        float res[8];
#pragma unroll
        for (int t = 0; t < 4; ++t) {
            float2 f = __half22float2(sp[t]);
            res[2 * t]     = fmaxf(fmaf(dii, f.x, acc[2 * t])     + bb[2 * t],     0.f);
            res[2 * t + 1] = fmaxf(fmaf(dii, f.y, acc[2 * t + 1]) + bb[2 * t + 1], 0.f);
        }
        uint4 ov;
        __half2 o0 = __float22half2_rn(make_float2(res[0], res[1]));
        __half2 o1 = __float22half2_rn(make_float2(res[2], res[3]));
        __half2 o2 = __float22half2_rn(make_float2(res[4], res[5]));
        __half2 o3 = __float22half2_rn(make_float2(res[6], res[7]));
        ov.x = *(uint32_t*)&o0; ov.y = *(uint32_t*)&o1;
        ov.z = *(uint32_t*)&o2; ov.w = *(uint32_t*)&o3;
        *(uint4*)(out + (size_t)i * 128 + sub * 8) = ov;
    }
}

// ---------------- host launch ----------------
extern "C" void kernel_launch(void* const* d_in, const int* in_sizes, int n_in,
                              void* d_out, int out_size)
{
    const float* x   = (const float*)d_in[0];
    const int*   ei  = (const int*)d_in[1];
    const float* W1  = (const float*)d_in[2];
    const float* b1  = (const float*)d_in[3];
    const float* W2  = (const float*)d_in[4];
    const float* b2  = (const float*)d_in[5];
    const float* W3  = (const float*)d_in[6];
    const float* b3  = (const float*)d_in[7];
    const float* fW1 = (const float*)d_in[8];
    const float* fb1 = (const float*)d_in[9];
    const float* fW2 = (const float*)d_in[10];
    const float* fb2 = (const float*)d_in[11];
    float* out = (float*)d_out;

    int N = in_sizes[0] / DIM;
    int E = in_sizes[1] / 2;
    const int* src = ei;
    const int* dst = ei + E;

    __half *bufH, *bufP, *wt;
    int* cntp;
    cudaGetSymbolAddress((void**)&bufH, g_bufH);
    cudaGetSymbolAddress((void**)&bufP, g_bufP);
    cudaGetSymbolAddress((void**)&wt,   g_Wt);
    cudaGetSymbolAddress((void**)&cntp, g_cnt);
    __half* Wt1 = wt;
    __half* Wt2 = wt + DIM * DIM;
    __half* Wt3 = wt + 2 * DIM * DIM;
    __half* Wt4 = wt + 3 * DIM * DIM;

    cudaFuncSetAttribute(k_gemm_mma, cudaFuncAttributeMaxDynamicSharedMemorySize,
                         (int)SMEM_BYTES);

    int nb256_E = (E + 255) / 256;
    int nbScan  = (N + SCAN_BS - 1) / SCAN_BS;
    int nT      = (N + 127) / 128;
    int nbGemm  = nT < 296 ? nT : 296;
    int nbAgg   = (N + 7) / 8;

    // fork/join: graph prep on side stream, transW+GEMM1 on main stream
    cudaStream_t s2;
    cudaEvent_t evF, evJ;
    cudaStreamCreateWithFlags(&s2, cudaStreamNonBlocking);
    cudaEventCreateWithFlags(&evF, cudaEventDisableTiming);
    cudaEventCreateWithFlags(&evJ, cudaEventDisableTiming);

    cudaMemsetAsync(cntp, 0, (size_t)N * sizeof(int));
    cudaEventRecord(evF, 0);
    cudaStreamWaitEvent(s2, evF, 0);

    // side stream: graph structure prep
    k_count_deg<<<nb256_E, 256, 0, s2>>>(dst, E);
    k_scan1<<<nbScan, SCAN_BS, 0, s2>>>(N);
    k_scan2<<<1, 128, 0, s2>>>(nbScan);
    k_scan3<<<nbScan, SCAN_BS, 0, s2>>>(N);
    k_scatter<<<nb256_E, 256, 0, s2>>>(src, dst, E);
    cudaEventRecord(evJ, s2);

    // main stream: weight transpose + layer-1 GEMM (independent of prep)
    dim3 trGrid(4, 4, 4), trBlk(32, 8);
    k_transW<<<trGrid, trBlk>>>(W1, W2, W3, fW1);
    k_gemm_mma<<<nbGemm, 256, SMEM_BYTES>>>(nullptr, x, Wt1, nullptr, bufH,
                                            nullptr, nullptr, nullptr, N, 0, 0, 0);

    // join: aggregation needs both GEMM1 output and CSR
    cudaStreamWaitEvent(0, evJ, 0);
    k_aggregate<<<nbAgg, 256>>>(bufH, b1, bufP, N);
    // layer 2
    k_gemm_mma<<<nbGemm, 256, SMEM_BYTES>>>(bufP, nullptr, Wt2, nullptr, bufH,
                                            nullptr, nullptr, nullptr, N, 0, 0, 0);
    k_aggregate<<<nbAgg, 256>>>(bufH, b2, bufP, N);
    // layer 3
    k_gemm_mma<<<nbGemm, 256, SMEM_BYTES>>>(bufP, nullptr, Wt3, nullptr, bufH,
                                            nullptr, nullptr, nullptr, N, 0, 0, 0);
    k_aggregate<<<nbAgg, 256>>>(bufH, b3, bufP, N);
    // FFN + fused head
    k_gemm_mma<<<nbGemm, 256, SMEM_BYTES>>>(bufP, nullptr, Wt4, fb1, nullptr,
                                            fW2, fb2, out, N, 1, 1, 1);

    cudaEventDestroy(evF);
    cudaEventDestroy(evJ);
    cudaStreamDestroy(s2);
}

// round 16
// speedup vs baseline: 1.1618x; 1.0053x over previous
#include <cuda_runtime.h>
#include <cuda_fp16.h>
#include <cuda_pipeline.h>
#include <cstdint>
#include <cstddef>

#define N_NODES   100000
#define N_EDGES   1600000
#define DIM       128
#define N_CLASSES 10

#define SCAN_BS   1024
#define SCAN_NB   ((N_NODES + SCAN_BS - 1) / SCAN_BS)   // 98 (<=128)

// ---------------- scratch (static __device__, no allocation) ----------------
__device__ __half g_bufH[(size_t)N_NODES * DIM];   // GEMM out h (gather target)
__device__ __half g_bufP[(size_t)N_NODES * DIM];   // aggregate out (GEMM A input)
__device__ __half g_Wt[4][DIM * DIM];              // transposed fp16 weights [n][k]
__device__ float  g_dinv[N_NODES];
__device__ int    g_cnt[N_NODES];
__device__ int    g_off[N_NODES + 1];
__device__ int    g_cur[N_NODES];
__device__ int2   g_edge[N_EDGES];                 // (src, norm bits)
__device__ int    g_bsum[SCAN_NB];
__device__ int    g_bpref[SCAN_NB];

// ---------------- prep kernels ----------------
__global__ void k_count_deg(const int* __restrict__ dst, int e) {
    int i = blockIdx.x * blockDim.x + threadIdx.x;
    if (i < e) atomicAdd(&g_cnt[dst[i]], 1);
}
__global__ void k_scan1(int n) {
    __shared__ int sh[SCAN_BS];
    int i = blockIdx.x * SCAN_BS + threadIdx.x;
    int c = (i < n) ? g_cnt[i] : 0;
    if (i < n) g_dinv[i] = rsqrtf((float)(c + 1));
    sh[threadIdx.x] = c;
    __syncthreads();
    for (int ofs = 1; ofs < SCAN_BS; ofs <<= 1) {
        int t = (threadIdx.x >= ofs) ? sh[threadIdx.x - ofs] : 0;
        __syncthreads();
        sh[threadIdx.x] += t;
        __syncthreads();
    }
    if (i < n) g_cur[i] = sh[threadIdx.x];
    if (threadIdx.x == SCAN_BS - 1) g_bsum[blockIdx.x] = sh[SCAN_BS - 1];
}
__global__ void k_scan2(int nb) {
    __shared__ int wsum[4];
    int t = threadIdx.x;
    int lane = t & 31, w = t >> 5;
    int v = (t < nb) ? g_bsum[t] : 0;
    int inc = v;
#pragma unroll
    for (int ofs = 1; ofs < 32; ofs <<= 1) {
        int u = __shfl_up_sync(0xFFFFFFFF, inc, ofs);
        if (lane >= ofs) inc += u;
    }
    if (lane == 31) wsum[w] = inc;
    __syncthreads();
    int woff = 0;
#pragma unroll
    for (int j = 0; j < 4; ++j) woff += (j < w) ? wsum[j] : 0;
    if (t < nb) g_bpref[t] = woff + inc - v;
}
__global__ void k_scan3(int n) {
    int i = blockIdx.x * SCAN_BS + threadIdx.x;
    if (i >= n) return;
    int inc = g_cur[i] + g_bpref[blockIdx.x];
    int ex = inc - g_cnt[i];
    g_off[i] = ex;
    g_cur[i] = ex;
    if (i == n - 1) g_off[n] = inc;
}
__global__ void k_scatter(const int* __restrict__ src, const int* __restrict__ dst, int e) {
    int i = blockIdx.x * blockDim.x + threadIdx.x;
    if (i >= e) return;
    int s = src[i], d = dst[i];
    int p = atomicAdd(&g_cur[d], 1);
    float nm = g_dinv[s] * g_dinv[d];
    g_edge[p] = make_int2(s, __float_as_int(nm));
}

__global__ void k_transW(const float* __restrict__ Wa, const float* __restrict__ Wb,
                         const float* __restrict__ Wc, const float* __restrict__ Wd) {
    __shared__ float tile[32][33];
    const float* W = (blockIdx.z == 0) ? Wa : (blockIdx.z == 1) ? Wb
                   : (blockIdx.z == 2) ? Wc : Wd;
    __half* Wt = g_Wt[blockIdx.z];
    int bn = blockIdx.x * 32, bk = blockIdx.y * 32;
    int tx = threadIdx.x, ty = threadIdx.y;
#pragma unroll
    for (int r = 0; r < 32; r += 8)
        tile[ty + r][tx] = W[(size_t)(bk + ty + r) * 128 + bn + tx];
    __syncthreads();
#pragma unroll
    for (int r = 0; r < 32; r += 8)
        Wt[(size_t)(bn + ty + r) * 128 + bk + tx] = __float2half_rn(tile[tx][ty + r]);
}

// ---------------- fp16 mma GEMM: ldmatrix fragments, persistent multi-tile ----------------
#define PADH 136
#define HPAD 129
#define SMEM_BYTES 106496

__device__ __forceinline__ void mma_f16(float c[4], const uint32_t a[4],
                                        uint32_t b0, uint32_t b1) {
    asm volatile(
        "mma.sync.aligned.m16n8k16.row.col.f32.f16.f16.f32 "
        "{%0,%1,%2,%3}, {%4,%5,%6,%7}, {%8,%9}, {%0,%1,%2,%3};"
        : "+f"(c[0]), "+f"(c[1]), "+f"(c[2]), "+f"(c[3])
        : "r"(a[0]), "r"(a[1]), "r"(a[2]), "r"(a[3]), "r"(b0), "r"(b1));
}

__device__ __forceinline__ void ldmx4(uint32_t r[4], uint32_t saddr) {
    asm volatile("ldmatrix.sync.aligned.m8n8.x4.shared.b16 {%0,%1,%2,%3}, [%4];"
        : "=r"(r[0]), "=r"(r[1]), "=r"(r[2]), "=r"(r[3]) : "r"(saddr));
}

__device__ __forceinline__ uint32_t s2u(const void* p) {
    return (uint32_t)__cvta_generic_to_shared(p);
}

// mainloop over K=128 with ldmatrix fragment loads
__device__ __forceinline__ void tile_mainloop(const __half* cur, const __half* sW,
                                              int wm, int wn, int lane,
                                              float acc[2][8][4])
{
    int l15 = lane & 15, l7 = lane & 7;
    int ahalf = (lane >> 4) << 3;          // A col offset: lanes 16-31 -> +8
    int brow8 = (lane >> 4) << 3;          // B row offset: lanes 16-31 -> +8
    int bcol8 = ((lane >> 3) & 1) << 3;    // B col offset: lane groups 1,3 -> +8
#pragma unroll
    for (int k0 = 0; k0 < 128; k0 += 16) {
        uint32_t a[2][4];
#pragma unroll
        for (int mf = 0; mf < 2; ++mf)
            ldmx4(a[mf], s2u(cur + (wm + mf * 16 + l15) * PADH + k0 + ahalf));
        uint32_t bb[4][4];
#pragma unroll
        for (int np = 0; np < 4; ++np) {
            int nc = wn + np * 16;
            ldmx4(bb[np], s2u(sW + (nc + l7 + brow8) * PADH + k0 + bcol8));
        }
#pragma unroll
        for (int np = 0; np < 4; ++np) {
            mma_f16(acc[0][2 * np],     a[0], bb[np][0], bb[np][1]);
            mma_f16(acc[1][2 * np],     a[1], bb[np][0], bb[np][1]);
            mma_f16(acc[0][2 * np + 1], a[0], bb[np][2], bb[np][3]);
            mma_f16(acc[1][2 * np + 1], a[1], bb[np][2], bb[np][3]);
        }
    }
}

__device__ __forceinline__ void prefetchA16(__half* dst, const __half* A16,
                                            int t, int M, int tid) {
#pragma unroll
    for (int i = 0; i < 8; ++i) {
        int fid = i * 256 + tid;
        int r = fid >> 4, c8 = (fid & 15) << 3;
        int gr = t * 128 + r;
        __half* d = dst + r * PADH + c8;
        if (gr < M)
            __pipeline_memcpy_async(d, A16 + (size_t)gr * 128 + c8, 16);
        else
            *(uint4*)d = make_uint4(0, 0, 0, 0);
    }
}

__global__ __launch_bounds__(256) void k_gemm_mma(
    const __half* __restrict__ A16, const float* __restrict__ A32,
    const __half* __restrict__ Wt, const float* __restrict__ bias,
    __half* __restrict__ C16,
    const float* __restrict__ W2, const float* __restrict__ b2,
    float* __restrict__ OutF,
    int M, int has_bias, int do_relu, int do_head)
{
    extern __shared__ __half smh[];
    __half* sW  = smh;                      // [128][PADH]
    __half* sA0 = smh + 128 * PADH;
    __half* sA1 = smh + 2 * 128 * PADH;

    int tid = threadIdx.x;
    int wid = tid >> 5, lane = tid & 31;
    int gID = lane >> 2, tig = lane & 3;
    int nT = (M + 127) >> 7;

    // stage W once per CTA
#pragma unroll
    for (int i = 0; i < 8; ++i) {
        int fid = i * 256 + tid;
        int n = fid >> 4, k8 = (fid & 15) << 3;
        *(uint4*)(sW + n * PADH + k8) = __ldg((const uint4*)(Wt + (size_t)n * 128 + k8));
    }

    int wm = (wid & 3) * 32;
    int wn = (wid >> 2) * 64;

    bool pipelined = (A32 == nullptr) && !do_head;

    if (pipelined) {
        int t0 = blockIdx.x;
        if (t0 < nT) prefetchA16(sA0, A16, t0, M, tid);
        __pipeline_commit();
        int it = 0;
        for (int t = t0; t < nT; t += gridDim.x, ++it) {
            __half* cur = (it & 1) ? sA1 : sA0;
            __half* nxt = (it & 1) ? sA0 : sA1;
            __pipeline_wait_prior(0);
            __syncthreads();
            int tn = t + gridDim.x;
            if (tn < nT) prefetchA16(nxt, A16, tn, M, tid);
            __pipeline_commit();

            float acc[2][8][4];
#pragma unroll
            for (int mf = 0; mf < 2; ++mf)
#pragma unroll
                for (int nf = 0; nf < 8; ++nf)
#pragma unroll
                    for (int j = 0; j < 4; ++j) acc[mf][nf][j] = 0.f;

            tile_mainloop(cur, sW, wm, wn, lane, acc);

            int row0 = t * 128;
#pragma unroll
            for (int mf = 0; mf < 2; ++mf) {
                int r_lo = row0 + wm + mf * 16 + gID;
                int r_hi = r_lo + 8;
#pragma unroll
                for (int nf = 0; nf < 8; ++nf) {
                    int col = wn + nf * 8 + tig * 2;
                    float2 vlo = make_float2(acc[mf][nf][0], acc[mf][nf][1]);
                    float2 vhi = make_float2(acc[mf][nf][2], acc[mf][nf][3]);
                    if (r_lo < M) *(__half2*)(C16 + (size_t)r_lo * 128 + col) = __float22half2_rn(vlo);
                    if (r_hi < M) *(__half2*)(C16 + (size_t)r_hi * 128 + col) = __float22half2_rn(vhi);
                }
            }
        }
        return;
    }

    // unpipelined multi-tile loop (A32 convert path, and/or fused-head path)
    for (int t = blockIdx.x; t < nT; t += gridDim.x) {
        __syncthreads();
        int row0 = t * 128;
        if (A32) {
#pragma unroll
            for (int i = 0; i < 16; ++i) {
                int fid = i * 256 + tid;
                int r = fid >> 5, c4 = (fid & 31) << 2;
                float4 v = make_float4(0.f, 0.f, 0.f, 0.f);
                int gr = row0 + r;
                if (gr < M) v = __ldg((const float4*)(A32 + (size_t)gr * 128 + c4));
                __half2 lo = __float22half2_rn(make_float2(v.x, v.y));
                __half2 hi = __float22half2_rn(make_float2(v.z, v.w));
                *(uint2*)(sA0 + r * PADH + c4) = make_uint2(*(uint32_t*)&lo, *(uint32_t*)&hi);
            }
        } else {
#pragma unroll
            for (int i = 0; i < 8; ++i) {
                int fid = i * 256 + tid;
                int r = fid >> 4, c8 = (fid & 15) << 3;
                uint4 v = make_uint4(0, 0, 0, 0);
                int gr = row0 + r;
                if (gr < M) v = __ldg((const uint4*)(A16 + (size_t)gr * 128 + c8));
                *(uint4*)(sA0 + r * PADH + c8) = v;
            }
        }
        __syncthreads();

        float acc[2][8][4];
#pragma unroll
        for (int mf = 0; mf < 2; ++mf)
#pragma unroll
            for (int nf = 0; nf < 8; ++nf)
#pragma unroll
                for (int j = 0; j < 4; ++j) acc[mf][nf][j] = 0.f;

        tile_mainloop(sA0, sW, wm, wn, lane, acc);

        if (!do_head) {
#pragma unroll
            for (int mf = 0; mf < 2; ++mf) {
                int r_lo = row0 + wm + mf * 16 + gID;
                int r_hi = r_lo + 8;
#pragma unroll
                for (int nf = 0; nf < 8; ++nf) {
                    int col = wn + nf * 8 + tig * 2;
                    float2 vlo = make_float2(acc[mf][nf][0], acc[mf][nf][1]);
                    float2 vhi = make_float2(acc[mf][nf][2], acc[mf][nf][3]);
                    if (has_bias) {
                        float bx = bias[col], by = bias[col + 1];
                        vlo.x += bx; vlo.y += by;
                        vhi.x += bx; vhi.y += by;
                    }
                    if (do_relu) {
                        vlo.x = fmaxf(vlo.x, 0.f); vlo.y = fmaxf(vlo.y, 0.f);
                        vhi.x = fmaxf(vhi.x, 0.f); vhi.y = fmaxf(vhi.y, 0.f);
                    }
                    if (r_lo < M) *(__half2*)(C16 + (size_t)r_lo * 128 + col) = __float22half2_rn(vlo);
                    if (r_hi < M) *(__half2*)(C16 + (size_t)r_hi * 128 + col) = __float22half2_rn(vhi);
                }
            }
        } else {
            __syncthreads();
            float* sT  = (float*)(smh + 128 * PADH);    // [128][HPAD]
            float* sW2 = sT + 128 * HPAD;
            float* sb2 = sW2 + 128 * N_CLASSES;

#pragma unroll
            for (int mf = 0; mf < 2; ++mf) {
                int lr_lo = wm + mf * 16 + gID;
                int lr_hi = lr_lo + 8;
#pragma unroll
                for (int nf = 0; nf < 8; ++nf) {
                    int col = wn + nf * 8 + tig * 2;
                    float bx = bias[col], by = bias[col + 1];
                    sT[lr_lo * HPAD + col]     = fmaxf(acc[mf][nf][0] + bx, 0.f);
                    sT[lr_lo * HPAD + col + 1] = fmaxf(acc[mf][nf][1] + by, 0.f);
                    sT[lr_hi * HPAD + col]     = fmaxf(acc[mf][nf][2] + bx, 0.f);
                    sT[lr_hi * HPAD + col + 1] = fmaxf(acc[mf][nf][3] + by, 0.f);
                }
            }
            for (int i = tid; i < 128 * N_CLASSES; i += 256) sW2[i] = __ldg(W2 + i);
            if (tid < N_CLASSES) sb2[tid] = b2[tid];
            __syncthreads();

            for (int o = tid; o < 128 * N_CLASSES; o += 256) {
                int r = o / N_CLASSES, c = o % N_CLASSES;
                int gr = row0 + r;
                if (gr >= M) continue;
                float s = sb2[c];
                const float* tr = sT + r * HPAD;
#pragma unroll
                for (int k = 0; k < 128; ++k)
                    s = fmaf(tr[k], sW2[k * N_CLASSES + c], s);
                OutF[(size_t)gr * N_CLASSES + c] = s;
            }
        }
    }
}

// ---------------- CSR aggregation: paired-edge LDG.128 (R14 proven) ----------------
__global__ __launch_bounds__(256) void k_aggregate(
    const __half* __restrict__ h, const float* __restrict__ bias,
    __half* __restrict__ out, int N)
{
    int warp = (blockIdx.x << 3) + (threadIdx.x >> 5);
    if (warp >= N) return;
    int i = warp;
    int lane = threadIdx.x & 31;
    int sub = lane & 15, half = lane >> 4;

    const __half* hcol = h + sub * 8;
    float acc[8];
#pragma unroll
    for (int t = 0; t < 8; ++t) acc[t] = 0.f;

    int e0 = g_off[i], e1 = g_off[i + 1];
    for (int e = e0; e < e1; e += 8) {
        int2 rec[4];
        uint4 hv[4];
#pragma unroll
        for (int k = 0; k < 4; ++k) {
            int idx = e + 2 * k + half;
            if (idx < e1) rec[k] = __ldg(&g_edge[idx]);
        }
#pragma unroll
        for (int k = 0; k < 4; ++k) {
            int idx = e + 2 * k + half;
            if (idx < e1) hv[k] = __ldg((const uint4*)(hcol + (size_t)rec[k].x * 128));
        }
#pragma unroll
        for (int k = 0; k < 4; ++k) {
            int idx = e + 2 * k + half;
            if (idx < e1) {
                float nm = __int_as_float(rec[k].y);
                const __half2* p = (const __half2*)&hv[k];
#pragma unroll
                for (int t = 0; t < 4; ++t) {
                    float2 f = __half22float2(p[t]);
                    acc[2 * t]     = fmaf(nm, f.x, acc[2 * t]);
                    acc[2 * t + 1] = fmaf(nm, f.y, acc[2 * t + 1]);
                }
            }
        }
    }

#pragma unroll
    for (int t = 0; t < 8; ++t)
        acc[t] += __shfl_xor_sync(0xFFFFFFFF, acc[t], 16);

    if (half == 0) {
        float di = g_dinv[i];
        float dii = di * di;
        uint4 us = __ldg((const uint4*)(hcol + (size_t)i * 128));
        const __half2* sp = (const __half2*)&us;
        float4 bv0 = __ldg((const float4*)(bias + sub * 8));
        float4 bv1 = __ldg((const float4*)(bias + sub * 8 + 4));
        float bb[8] = {bv0.x, bv0.y, bv0.z, bv0.w, bv1.x, bv1.y, bv1.z, bv1.w};
        float res[8];
#pragma unroll
        for (int t = 0; t < 4; ++t) {
            float2 f = __half22float2(sp[t]);
            res[2 * t]     = fmaxf(fmaf(dii, f.x, acc[2 * t])     + bb[2 * t],     0.f);
            res[2 * t + 1] = fmaxf(fmaf(dii, f.y, acc[2 * t + 1]) + bb[2 * t + 1], 0.f);
        }
        uint4 ov;
        __half2 o0 = __float22half2_rn(make_float2(res[0], res[1]));
        __half2 o1 = __float22half2_rn(make_float2(res[2], res[3]));
        __half2 o2 = __float22half2_rn(make_float2(res[4], res[5]));
        __half2 o3 = __float22half2_rn(make_float2(res[6], res[7]));
        ov.x = *(uint32_t*)&o0; ov.y = *(uint32_t*)&o1;
        ov.z = *(uint32_t*)&o2; ov.w = *(uint32_t*)&o3;
        *(uint4*)(out + (size_t)i * 128 + sub * 8) = ov;
    }
}

// ---------------- host launch ----------------
extern "C" void kernel_launch(void* const* d_in, const int* in_sizes, int n_in,
                              void* d_out, int out_size)
{
    const float* x   = (const float*)d_in[0];
    const int*   ei  = (const int*)d_in[1];
    const float* W1  = (const float*)d_in[2];
    const float* b1  = (const float*)d_in[3];
    const float* W2  = (const float*)d_in[4];
    const float* b2  = (const float*)d_in[5];
    const float* W3  = (const float*)d_in[6];
    const float* b3  = (const float*)d_in[7];
    const float* fW1 = (const float*)d_in[8];
    const float* fb1 = (const float*)d_in[9];
    const float* fW2 = (const float*)d_in[10];
    const float* fb2 = (const float*)d_in[11];
    float* out = (float*)d_out;

    int N = in_sizes[0] / DIM;
    int E = in_sizes[1] / 2;
    const int* src = ei;
    const int* dst = ei + E;

    __half *bufH, *bufP, *wt;
    int* cntp;
    cudaGetSymbolAddress((void**)&bufH, g_bufH);
    cudaGetSymbolAddress((void**)&bufP, g_bufP);
    cudaGetSymbolAddress((void**)&wt,   g_Wt);
    cudaGetSymbolAddress((void**)&cntp, g_cnt);
    __half* Wt1 = wt;
    __half* Wt2 = wt + DIM * DIM;
    __half* Wt3 = wt + 2 * DIM * DIM;
    __half* Wt4 = wt + 3 * DIM * DIM;

    cudaFuncSetAttribute(k_gemm_mma, cudaFuncAttributeMaxDynamicSharedMemorySize,
                         (int)SMEM_BYTES);

    int nb256_E = (E + 255) / 256;
    int nbScan  = (N + SCAN_BS - 1) / SCAN_BS;
    int nT      = (N + 127) / 128;
    int nbGemm  = nT < 296 ? nT : 296;
    int nbAgg   = (N + 7) / 8;

    // fork/join: graph prep on side stream, transW+GEMM1 on main stream
    cudaStream_t s2;
    cudaEvent_t evF, evJ;
    cudaStreamCreateWithFlags(&s2, cudaStreamNonBlocking);
    cudaEventCreateWithFlags(&evF, cudaEventDisableTiming);
    cudaEventCreateWithFlags(&evJ, cudaEventDisableTiming);

    cudaMemsetAsync(cntp, 0, (size_t)N * sizeof(int));
    cudaEventRecord(evF, 0);
    cudaStreamWaitEvent(s2, evF, 0);

    // side stream: graph structure prep
    k_count_deg<<<nb256_E, 256, 0, s2>>>(dst, E);
    k_scan1<<<nbScan, SCAN_BS, 0, s2>>>(N);
    k_scan2<<<1, 128, 0, s2>>>(nbScan);
    k_scan3<<<nbScan, SCAN_BS, 0, s2>>>(N);
    k_scatter<<<nb256_E, 256, 0, s2>>>(src, dst, E);
    cudaEventRecord(evJ, s2);

    // main stream: weight transpose + layer-1 GEMM (independent of prep)
    dim3 trGrid(4, 4, 4), trBlk(32, 8);
    k_transW<<<trGrid, trBlk>>>(W1, W2, W3, fW1);
    k_gemm_mma<<<nbGemm, 256, SMEM_BYTES>>>(nullptr, x, Wt1, nullptr, bufH,
                                            nullptr, nullptr, nullptr, N, 0, 0, 0);

    // join: aggregation needs both GEMM1 output and CSR
    cudaStreamWaitEvent(0, evJ, 0);
    k_aggregate<<<nbAgg, 256>>>(bufH, b1, bufP, N);
    // layer 2
    k_gemm_mma<<<nbGemm, 256, SMEM_BYTES>>>(bufP, nullptr, Wt2, nullptr, bufH,
                                            nullptr, nullptr, nullptr, N, 0, 0, 0);
    k_aggregate<<<nbAgg, 256>>>(bufH, b2, bufP, N);
    // layer 3
    k_gemm_mma<<<nbGemm, 256, SMEM_BYTES>>>(bufP, nullptr, Wt3, nullptr, bufH,
                                            nullptr, nullptr, nullptr, N, 0, 0, 0);
    k_aggregate<<<nbAgg, 256>>>(bufH, b3, bufP, N);
    // FFN + fused head
    k_gemm_mma<<<nbGemm, 256, SMEM_BYTES>>>(bufP, nullptr, Wt4, fb1, nullptr,
                                            fW2, fb2, out, N, 1, 1, 1);

    cudaEventDestroy(evF);
    cudaEventDestroy(evJ);
    cudaStreamDestroy(s2);
}